// round 5
// baseline (speedup 1.0000x reference)
#include <cuda_runtime.h>
#include <math.h>

#define Bv 64
#define Tv 512
#define Iv 512
#define Hv 1024
#define Cv 128
#define G3 (3*Hv)
#define G2 (2*Hv)

// ---- static device scratch (no runtime allocation) ----
__device__ float g_xw_f[(size_t)Tv*Bv*G3];   // forward GRU input projections  [t*B+b, 3H]
__device__ float g_xw_b[(size_t)Tv*Bv*G3];   // backward GRU input projections
__device__ float g_xzr [(size_t)Tv*Bv*G2];   // TAGM zr input projections      [t*B+b, 2H]
__device__ float g_xt  [(size_t)Tv*Bv*Hv];   // TAGM t  input projections      [t*B+b, H]
__device__ float g_hf  [(size_t)Tv*Bv*Hv];   // forward GRU hidden states per t
__device__ float g_hb  [(size_t)Tv*Bv*Hv];   // backward GRU hidden states per t
__device__ float g_hh  [(size_t)Tv*Bv*Hv];   // TAGM hidden history (one slot per step)
__device__ float g_att [Tv*Bv];              // attention gate a[t,b]
// split-K partial buffers (address-reused every step -> readers use __ldcg)
__device__ float g_pgru[(size_t)4*2*Bv*G3];  // [kb][dir][b][3072]
__device__ float g_ptag[(size_t)8*Bv*G3];    // [kb][b][3072]

// grid-barrier state: 3 groups (fwd GRU, bwd GRU, TAGM), padded lines
__device__ unsigned g_bar_cnt[3*32];
__device__ unsigned g_bar_gen[3*32];

__device__ __forceinline__ float sigmoidf_(float x) { return 1.0f / (1.0f + expf(-x)); }

// packed f32x2 FMA: d(lo,hi) += a(lo,hi) * b(lo,hi)
__device__ __forceinline__ void fma2(unsigned long long& d,
                                     unsigned long long a, unsigned long long b) {
    asm("fma.rn.f32x2 %0, %1, %2, %0;" : "+l"(d) : "l"(a), "l"(b));
}
__device__ __forceinline__ float hsum2(unsigned long long v) {
    float lo, hi;
    asm("mov.b64 {%0,%1}, %2;" : "=f"(lo), "=f"(hi) : "l"(v));
    return lo + hi;
}

// sense-reversing grid barrier among nb blocks (group grp)
__device__ __forceinline__ void grid_bar(int grp, unsigned nb) {
    volatile unsigned* gen = (volatile unsigned*)&g_bar_gen[grp*32];
    unsigned* cnt = &g_bar_cnt[grp*32];
    __threadfence();
    __syncthreads();
    if (threadIdx.x == 0) {
        unsigned g = *gen;
        if (atomicAdd(cnt, 1u) == nb - 1) {
            atomicExch(cnt, 0u);
            __threadfence();
            *gen = g + 1;
        } else {
            while (*gen == g) __nanosleep(64);
            __threadfence();
        }
    }
    __syncthreads();
}

// ============================================================================
// Input projection GEMM: out[r, n] = sum_i x_tb(r,i) * W[n,i] + bias[n]
// ============================================================================
__global__ void __launch_bounds__(256, 2) proj_gemm(
    const float* __restrict__ x, const float* __restrict__ W,
    const float* __restrict__ bias, float* __restrict__ out, int N)
{
    __shared__ __align__(16) float sa[128][36];
    __shared__ __align__(16) float sw[64][36];

    const int tid = threadIdx.x;
    const int tx = tid & 15;
    const int ty = tid >> 4;
    const int m0 = blockIdx.y * 128;
    const int n0 = blockIdx.x * 64;

    unsigned long long acc[8][4] = {};

    for (int k0 = 0; k0 < Iv; k0 += 16) {
        #pragma unroll
        for (int q = 0; q < 2; q++) {
            int idx = tid + 256 * q;
            int m = idx >> 2, kq = idx & 3;
            int r = m0 + m;
            int b = r & 63, t = r >> 6;
            float4 v = *(const float4*)(x + ((size_t)b * Tv + t) * Iv + k0 + kq * 4);
            *(float4*)&sa[m][kq * 4] = v;
        }
        {
            int n = tid >> 2, kq = tid & 3;
            float4 v = *(const float4*)(W + (size_t)(n0 + n) * Iv + k0 + kq * 4);
            *(float4*)&sw[n][kq * 4] = v;
        }
        __syncthreads();
        #pragma unroll
        for (int kq = 0; kq < 4; kq++) {
            ulonglong2 wv[4];
            #pragma unroll
            for (int nn = 0; nn < 4; nn++)
                wv[nn] = *(const ulonglong2*)&sw[tx + nn * 16][kq * 4];
            #pragma unroll
            for (int mm = 0; mm < 8; mm++) {
                ulonglong2 av = *(const ulonglong2*)&sa[ty + mm * 16][kq * 4];
                #pragma unroll
                for (int nn = 0; nn < 4; nn++) {
                    fma2(acc[mm][nn], av.x, wv[nn].x);
                    fma2(acc[mm][nn], av.y, wv[nn].y);
                }
            }
        }
        __syncthreads();
    }

    #pragma unroll
    for (int mm = 0; mm < 8; mm++) {
        int r = m0 + ty + mm * 16;
        #pragma unroll
        for (int nn = 0; nn < 4; nn++) {
            int n = n0 + tx + nn * 16;
            out[(size_t)r * N + n] = hsum2(acc[mm][nn]) + bias[n];
        }
    }
}

// ============================================================================
// Persistent bidirectional GRU with split-K.
//   256 blocks x 128 thr (2/SM). dir = blk>>7. Within dir (bid 0..127):
//   Phase A: gate-tile gt=bid>>2 (96 gates), k-split kb=bid&3 (k=256),
//            8b x 6g microtile per thread (FFMA2, k-packed) -> partials.
//   Phase B: j0=bid*8 -> reduce partials, gate nonlinearity, write h(t).
// ============================================================================
__global__ void __launch_bounds__(128, 2) gru_persist(
    const float* __restrict__ wh_f, const float* __restrict__ wh_b,
    const float* __restrict__ bh_f, const float* __restrict__ bh_b)
{
    __shared__ __align__(16) float sh[64][68];
    __shared__ __align__(16) float sw[96][68];

    const int tid = threadIdx.x;
    const int dir = blockIdx.x >> 7;
    const int bid = blockIdx.x & 127;
    const int gt  = bid >> 2;      // 0..31
    const int kb  = bid & 3;       // 0..3
    const int gx  = tid & 15;      // g-lane
    const int by  = tid >> 4;      // 0..7 (b-group of 8)
    const int jl  = tid & 7;
    const int bq  = tid >> 3;      // 0..15

    const float* wh = dir ? wh_b : wh_f;
    const float* bh = dir ? bh_b : bh_f;
    const float* xwbase = dir ? g_xw_b : g_xw_f;
    float* hbuf = dir ? g_hb : g_hf;
    float* mypart = g_pgru + ((size_t)(kb * 2 + dir)) * Bv * G3;

    const int j = bid * 8 + jl;
    const float bhr = bh[j], bhz = bh[Hv + j], bhn = bh[2*Hv + j];
    const float* wrow = wh + (size_t)(gt * 96) * Hv;

    for (int s = 0; s < Tv; s++) {
        const int t = dir ? (Tv - 1 - s) : s;
        const int tprev = dir ? t + 1 : t - 1;

        // ---------------- phase A: partial GEMM ----------------
        if (s) {
            const float* hp = hbuf + (size_t)tprev * Bv * Hv;
            unsigned long long acc[8][6] = {};
            #pragma unroll 1
            for (int c = 0; c < 4; c++) {
                const int k0 = kb * 256 + c * 64;
                #pragma unroll
                for (int u = 0; u < 8; u++) {
                    int idx = tid + 128 * u;
                    int bb = idx >> 4, kq = idx & 15;
                    *(float4*)&sh[bb][kq * 4] =
                        *(const float4*)(hp + (size_t)bb * Hv + k0 + kq * 4);
                }
                #pragma unroll
                for (int u = 0; u < 12; u++) {
                    int idx = tid + 128 * u;
                    int r = idx >> 4, kq = idx & 15;
                    *(float4*)&sw[r][kq * 4] =
                        *(const float4*)(wrow + (size_t)r * Hv + k0 + kq * 4);
                }
                __syncthreads();
                #pragma unroll
                for (int kk = 0; kk < 16; kk++) {
                    ulonglong2 wv[6];
                    #pragma unroll
                    for (int v = 0; v < 6; v++)
                        wv[v] = *(const ulonglong2*)&sw[gx + 16 * v][kk * 4];
                    #pragma unroll
                    for (int u = 0; u < 8; u++) {
                        ulonglong2 hv = *(const ulonglong2*)&sh[by * 8 + u][kk * 4];
                        #pragma unroll
                        for (int v = 0; v < 6; v++) {
                            fma2(acc[u][v], hv.x, wv[v].x);
                            fma2(acc[u][v], hv.y, wv[v].y);
                        }
                    }
                }
                __syncthreads();
            }
            #pragma unroll
            for (int u = 0; u < 8; u++) {
                float* prow = mypart + (size_t)(by * 8 + u) * G3 + gt * 96 + gx;
                #pragma unroll
                for (int v = 0; v < 6; v++)
                    prow[16 * v] = hsum2(acc[u][v]);
            }
        }

        grid_bar(dir, 128);

        // ---------------- phase B: reduce + gates ----------------
        {
            const float* xw = xwbase + (size_t)t * Bv * G3;
            float* hcur = hbuf + (size_t)t * Bv * Hv;
            const float* hp = hbuf + (size_t)(s ? tprev : t) * Bv * Hv;
            #pragma unroll
            for (int u = 0; u < 4; u++) {
                int b = bq * 4 + u;
                float ra = 0.f, za = 0.f, na = 0.f;
                if (s) {
                    #pragma unroll
                    for (int k2 = 0; k2 < 4; k2++) {
                        const float* p = g_pgru + ((size_t)(k2 * 2 + dir)) * Bv * G3
                                       + (size_t)b * G3;
                        ra += __ldcg(p + j);
                        za += __ldcg(p + Hv + j);
                        na += __ldcg(p + 2 * Hv + j);
                    }
                }
                const float* xwb = xw + (size_t)b * G3;
                float r = sigmoidf_(xwb[j]          + ra + bhr);
                float z = sigmoidf_(xwb[Hv + j]     + za + bhz);
                float n = tanhf    (xwb[2*Hv + j]   + r * (na + bhn));
                float hpv = s ? hp[(size_t)b * Hv + j] : 0.0f;
                hcur[(size_t)b * Hv + j] = (1.0f - z) * n + z * hpv;
            }
        }

        if (s != Tv - 1) grid_bar(dir, 128);
    }
}

// ============================================================================
// Attention logits
// ============================================================================
__global__ void att_kernel(const float* __restrict__ fcw, const float* __restrict__ fcb,
                           float* __restrict__ out_att)
{
    const int t = blockIdx.x;
    const int w = threadIdx.x >> 5, lane = threadIdx.x & 31;
    for (int rep = 0; rep < 8; rep++) {
        int b = w + rep * 8;
        const float* hf = g_hf + (size_t)(t * Bv + b) * Hv;
        const float* hb = g_hb + (size_t)(t * Bv + b) * Hv;
        float acc = 0.0f;
        for (int k = lane; k < Hv; k += 32)
            acc += hf[k] * fcw[k] + hb[k] * fcw[Hv + k];
        #pragma unroll
        for (int o = 16; o; o >>= 1) acc += __shfl_xor_sync(0xffffffffu, acc, o);
        if (lane == 0) {
            float a = sigmoidf_(3.0f * (acc + fcb[0]));
            g_att[t * Bv + b] = a;
            out_att[(size_t)b * Tv + t] = a;
        }
    }
}

// ============================================================================
// Persistent TAGM with split-K: 256 blocks x 128 thr.
//   Phase A: gt=bid>>3 (96 gates), kb=bid&7 (k=128). Virtual weight rows:
//   g<2048 -> wzr[g], else wt[g-2048].
//   Phase B: j0=bid*4, 2 outputs/thread, reduce 8 k-splits.
// ============================================================================
__global__ void __launch_bounds__(128, 2) tagm_persist(
    const float* __restrict__ wzr, const float* __restrict__ bzr,
    const float* __restrict__ wt,  const float* __restrict__ bt)
{
    __shared__ __align__(16) float sh[64][68];
    __shared__ __align__(16) float sw[96][68];

    const int tid = threadIdx.x;
    const int bid = blockIdx.x;    // 0..255
    const int gt  = bid >> 3;      // 0..31
    const int kb  = bid & 7;       // 0..7
    const int gx  = tid & 15;
    const int by  = tid >> 4;
    const int jl  = tid & 3;
    const int bqq = tid >> 2;      // 0..31

    float* mypart = g_ptag + (size_t)kb * Bv * G3;
    const int j = bid * 4 + jl;
    const float br = bzr[j], bz = bzr[Hv + j], btt = bt[j];

    for (int s = 0; s < Tv; s++) {
        // ---------------- phase A ----------------
        if (s) {
            const float* hp = g_hh + (size_t)(s - 1) * Bv * Hv;
            unsigned long long acc[8][6] = {};
            #pragma unroll 1
            for (int c = 0; c < 2; c++) {
                const int k0 = kb * 128 + c * 64;
                #pragma unroll
                for (int u = 0; u < 8; u++) {
                    int idx = tid + 128 * u;
                    int bb = idx >> 4, kq = idx & 15;
                    *(float4*)&sh[bb][kq * 4] =
                        *(const float4*)(hp + (size_t)bb * Hv + k0 + kq * 4);
                }
                #pragma unroll
                for (int u = 0; u < 12; u++) {
                    int idx = tid + 128 * u;
                    int r = idx >> 4, kq = idx & 15;
                    int gr = gt * 96 + r;
                    const float* src = (gr < G2) ? (wzr + (size_t)gr * Hv)
                                                 : (wt + (size_t)(gr - G2) * Hv);
                    *(float4*)&sw[r][kq * 4] = *(const float4*)(src + k0 + kq * 4);
                }
                __syncthreads();
                #pragma unroll
                for (int kk = 0; kk < 16; kk++) {
                    ulonglong2 wv[6];
                    #pragma unroll
                    for (int v = 0; v < 6; v++)
                        wv[v] = *(const ulonglong2*)&sw[gx + 16 * v][kk * 4];
                    #pragma unroll
                    for (int u = 0; u < 8; u++) {
                        ulonglong2 hv = *(const ulonglong2*)&sh[by * 8 + u][kk * 4];
                        #pragma unroll
                        for (int v = 0; v < 6; v++) {
                            fma2(acc[u][v], hv.x, wv[v].x);
                            fma2(acc[u][v], hv.y, wv[v].y);
                        }
                    }
                }
                __syncthreads();
            }
            #pragma unroll
            for (int u = 0; u < 8; u++) {
                float* prow = mypart + (size_t)(by * 8 + u) * G3 + gt * 96 + gx;
                #pragma unroll
                for (int v = 0; v < 6; v++)
                    prow[16 * v] = hsum2(acc[u][v]);
            }
        }

        grid_bar(2, 256);

        // ---------------- phase B ----------------
        {
            const float* hp = g_hh + (size_t)(s ? s - 1 : 0) * Bv * Hv;
            float* hnext = g_hh + (size_t)s * Bv * Hv;
            #pragma unroll
            for (int u = 0; u < 2; u++) {
                int b = bqq + 32 * u;
                float ra = 0.f, za = 0.f, na = 0.f;
                if (s) {
                    #pragma unroll
                    for (int k2 = 0; k2 < 8; k2++) {
                        const float* p = g_ptag + (size_t)k2 * Bv * G3 + (size_t)b * G3;
                        ra += __ldcg(p + j);
                        za += __ldcg(p + Hv + j);
                        na += __ldcg(p + 2 * Hv + j);
                    }
                }
                const float* xzrb = g_xzr + (size_t)(s * Bv + b) * G2;
                float a  = g_att[s * Bv + b];
                float r  = sigmoidf_(xzrb[j]      + ra + br);
                float z  = sigmoidf_(xzrb[Hv + j] + za + bz);
                float ht = tanhf(g_xt[(size_t)(s * Bv + b) * Hv + j] + r * (na + btt));
                float hpv = s ? hp[(size_t)b * Hv + j] : 0.0f;
                hnext[(size_t)b * Hv + j] = a * (z * ht + (1.0f - z) * hpv);
            }
        }

        if (s != Tv - 1) grid_bar(2, 256);
    }
}

// ============================================================================
// fc0: out[b,c] = h_last[b,:] . fc0_w[c,:] + fc0_b[c]
// ============================================================================
__global__ void fc0_kernel(const float* __restrict__ w, const float* __restrict__ bias,
                           float* __restrict__ out)
{
    const int b = blockIdx.x;
    const int wp = threadIdx.x >> 5, lane = threadIdx.x & 31;
    const float* h = g_hh + (size_t)(Tv - 1) * Bv * Hv + (size_t)b * Hv;
    for (int c = wp; c < Cv; c += 8) {
        float acc = 0.0f;
        for (int k = lane; k < Hv; k += 32) acc += h[k] * w[(size_t)c * Hv + k];
        #pragma unroll
        for (int o = 16; o; o >>= 1) acc += __shfl_xor_sync(0xffffffffu, acc, o);
        if (lane == 0) out[(size_t)b * Cv + c] = acc + bias[c];
    }
}

// ============================================================================
extern "C" void kernel_launch(void* const* d_in, const int* in_sizes, int n_in,
                              void* d_out, int out_size)
{
    const float* x        = (const float*)d_in[0];
    const float* att_wi_f = (const float*)d_in[1];
    const float* att_wh_f = (const float*)d_in[2];
    const float* att_bi_f = (const float*)d_in[3];
    const float* att_bh_f = (const float*)d_in[4];
    const float* att_wi_b = (const float*)d_in[5];
    const float* att_wh_b = (const float*)d_in[6];
    const float* att_bi_b = (const float*)d_in[7];
    const float* att_bh_b = (const float*)d_in[8];
    const float* att_fc_w = (const float*)d_in[9];
    const float* att_fc_b = (const float*)d_in[10];
    const float* w_i2h_zr = (const float*)d_in[11];
    const float* b_i2h_zr = (const float*)d_in[12];
    const float* w_h2h_zr = (const float*)d_in[13];
    const float* b_h2h_zr = (const float*)d_in[14];
    const float* w_i2h_t  = (const float*)d_in[15];
    const float* b_i2h_t  = (const float*)d_in[16];
    const float* w_h2h_t  = (const float*)d_in[17];
    const float* b_h2h_t  = (const float*)d_in[18];
    const float* fc0_w    = (const float*)d_in[19];
    const float* fc0_b    = (const float*)d_in[20];

    float* out     = (float*)d_out;
    float* out_att = out + Bv * Cv;

    float *p_xwf, *p_xwb, *p_xzr, *p_xt;
    cudaGetSymbolAddress((void**)&p_xwf, g_xw_f);
    cudaGetSymbolAddress((void**)&p_xwb, g_xw_b);
    cudaGetSymbolAddress((void**)&p_xzr, g_xzr);
    cudaGetSymbolAddress((void**)&p_xt,  g_xt);

    // 1) input projections
    proj_gemm<<<dim3(G3 / 64, (Tv * Bv) / 128), 256>>>(x, att_wi_f, att_bi_f, p_xwf, G3);
    proj_gemm<<<dim3(G3 / 64, (Tv * Bv) / 128), 256>>>(x, att_wi_b, att_bi_b, p_xwb, G3);
    proj_gemm<<<dim3(G2 / 64, (Tv * Bv) / 128), 256>>>(x, w_i2h_zr, b_i2h_zr, p_xzr, G2);
    proj_gemm<<<dim3(Hv / 64, (Tv * Bv) / 128), 256>>>(x, w_i2h_t,  b_i2h_t,  p_xt,  Hv);

    // 2) bidirectional GRU — persistent, split-K
    gru_persist<<<256, 128>>>(att_wh_f, att_wh_b, att_bh_f, att_bh_b);

    // 3) attention gate
    att_kernel<<<Tv, 256>>>(att_fc_w, att_fc_b, out_att);

    // 4) TAGM — persistent, split-K
    tagm_persist<<<256, 128>>>(w_h2h_zr, b_h2h_zr, w_h2h_t, b_h2h_t);

    // 5) final projection
    fc0_kernel<<<Bv, 256>>>(fc0_w, fc0_b, out);
}

// round 6
// speedup vs baseline: 1.4793x; 1.4793x over previous
#include <cuda_runtime.h>
#include <cuda_bf16.h>
#include <math.h>
#include <stdint.h>

#define Bv 64
#define Tv 512
#define Iv 512
#define Hv 1024
#define Cv 128
#define G3 (3*Hv)
#define G2 (2*Hv)

// ---------------- static device scratch ----------------
__device__ float g_xw_f[(size_t)Tv*Bv*G3];
__device__ float g_xw_b[(size_t)Tv*Bv*G3];
__device__ float g_xzr [(size_t)Tv*Bv*G2];
__device__ float g_xt  [(size_t)Tv*Bv*Hv];
__device__ float g_att [Tv*Bv];

// packed bf16-pair words (word w = elems 2w (lo16), 2w+1 (hi16))
__device__ uint32_t g_xh[(size_t)32768*256], g_xl[(size_t)32768*256];
__device__ uint32_t g_wif_h[(size_t)3072*256],  g_wif_l[(size_t)3072*256];
__device__ uint32_t g_wib_h[(size_t)3072*256],  g_wib_l[(size_t)3072*256];
__device__ uint32_t g_wizr_h[(size_t)2048*256], g_wizr_l[(size_t)2048*256];
__device__ uint32_t g_wit_h[(size_t)1024*256],  g_wit_l[(size_t)1024*256];
// hidden-state histories, split-bf16 words [t][b][512]
__device__ uint32_t g_hf_h[(size_t)Tv*Bv*512], g_hf_l[(size_t)Tv*Bv*512];
__device__ uint32_t g_hb_h[(size_t)Tv*Bv*512], g_hb_l[(size_t)Tv*Bv*512];
__device__ uint32_t g_ht_h[(size_t)Tv*Bv*512], g_ht_l[(size_t)Tv*Bv*512];

__device__ unsigned g_bar_cnt[3*32];
__device__ unsigned g_bar_gen[3*32];

__device__ __forceinline__ float sigmoidf_(float x) { return 1.0f / (1.0f + expf(-x)); }
__device__ __forceinline__ float lo16f(uint32_t w) { return __uint_as_float(w << 16); }
__device__ __forceinline__ float hi16f(uint32_t w) { return __uint_as_float(w & 0xffff0000u); }
__device__ __forceinline__ uint32_t bfbits(float x) {
    __nv_bfloat16 h = __float2bfloat16(x);
    return (uint32_t)*reinterpret_cast<unsigned short*>(&h);
}
__device__ __forceinline__ void split2(float x0, float x1, uint32_t& wh, uint32_t& wl) {
    uint32_t h0 = bfbits(x0), h1 = bfbits(x1);
    float r0 = x0 - __uint_as_float(h0 << 16);
    float r1 = x1 - __uint_as_float(h1 << 16);
    wh = h0 | (bfbits(x1) << 16);
    wh = h0 | (h1 << 16);
    wl = bfbits(r0) | (bfbits(r1) << 16);
}

__device__ __forceinline__ void mma16816(float* d,
    uint32_t a0, uint32_t a1, uint32_t a2, uint32_t a3, uint32_t b0, uint32_t b1) {
    asm volatile(
        "mma.sync.aligned.m16n8k16.row.col.f32.bf16.bf16.f32 "
        "{%0,%1,%2,%3},{%4,%5,%6,%7},{%8,%9},{%0,%1,%2,%3};"
        : "+f"(d[0]), "+f"(d[1]), "+f"(d[2]), "+f"(d[3])
        : "r"(a0), "r"(a1), "r"(a2), "r"(a3), "r"(b0), "r"(b1));
}

__device__ __forceinline__ void grid_bar(int grp, unsigned nb) {
    volatile unsigned* gen = (volatile unsigned*)&g_bar_gen[grp*32];
    unsigned* cnt = &g_bar_cnt[grp*32];
    __threadfence();
    __syncthreads();
    if (threadIdx.x == 0) {
        unsigned g = *gen;
        if (atomicAdd(cnt, 1u) == nb - 1) {
            atomicExch(cnt, 0u);
            __threadfence();
            *gen = g + 1;
        } else {
            while (*gen == g) __nanosleep(64);
            __threadfence();
        }
    }
    __syncthreads();
}

// ============================================================================
// converters
// ============================================================================
__global__ void conv_x(const float* __restrict__ x) {
    int r = blockIdx.x, wi = threadIdx.x;          // r = t*64+b
    int b = r & 63, t = r >> 6;
    float2 v = ((const float2*)x)[((size_t)b * Tv + t) * 256 + wi];
    uint32_t wh, wl; split2(v.x, v.y, wh, wl);
    g_xh[(size_t)r * 256 + wi] = wh;
    g_xl[(size_t)r * 256 + wi] = wl;
}
__global__ void conv_w(const float* __restrict__ src,
                       uint32_t* __restrict__ hi, uint32_t* __restrict__ lo) {
    size_t i = (size_t)blockIdx.x * 256 + threadIdx.x;
    float2 v = ((const float2*)src)[i];
    uint32_t wh, wl; split2(v.x, v.y, wh, wl);
    hi[i] = wh; lo[i] = wl;
}

// ============================================================================
// proj via bf16-split mma: out[r,n] = x[r,:].W[n,:] + bias[n]; tile 64x64xK512
// ============================================================================
__global__ void __launch_bounds__(128) proj_mma(
    const uint32_t* __restrict__ Ah, const uint32_t* __restrict__ Al,
    const uint32_t* __restrict__ Wh, const uint32_t* __restrict__ Wl,
    const float* __restrict__ bias, float* __restrict__ out, int N)
{
    __shared__ uint32_t sA[2*64*36], sB[2*64*36];   // hi at 0, lo at +2304
    const int tid = threadIdx.x, w = tid >> 5, lane = tid & 31;
    const int g = lane >> 2, tg = lane & 3;
    const int m0 = blockIdx.y * 64, n0 = blockIdx.x * 64;

    float D[8][4] = {};

    #pragma unroll 1
    for (int st = 0; st < 8; st++) {
        const int kw0 = st * 32;
        __syncthreads();
        #pragma unroll
        for (int q = 0; q < 4; q++) {
            int idx = tid + 128 * q;
            int row = idx >> 3, seg = idx & 7;
            *(uint4*)&sA[row*36 + seg*4]        = *(const uint4*)(Ah + (size_t)(m0+row)*256 + kw0 + seg*4);
            *(uint4*)&sA[2304 + row*36 + seg*4] = *(const uint4*)(Al + (size_t)(m0+row)*256 + kw0 + seg*4);
            *(uint4*)&sB[row*36 + seg*4]        = *(const uint4*)(Wh + (size_t)(n0+row)*256 + kw0 + seg*4);
            *(uint4*)&sB[2304 + row*36 + seg*4] = *(const uint4*)(Wl + (size_t)(n0+row)*256 + kw0 + seg*4);
        }
        __syncthreads();
        #pragma unroll
        for (int ks = 0; ks < 4; ks++) {
            int ra = (16*w + g) * 36 + ks * 8, rb = ra + 8*36;
            uint32_t a0h = sA[ra+tg],      a2h = sA[ra+4+tg];
            uint32_t a1h = sA[rb+tg],      a3h = sA[rb+4+tg];
            uint32_t a0l = sA[2304+ra+tg], a2l = sA[2304+ra+4+tg];
            uint32_t a1l = sA[2304+rb+tg], a3l = sA[2304+rb+4+tg];
            #pragma unroll
            for (int nt = 0; nt < 8; nt++) {
                int rn = (nt*8 + g) * 36 + ks * 8;
                uint32_t b0h = sB[rn+tg],      b1h = sB[rn+4+tg];
                uint32_t b0l = sB[2304+rn+tg], b1l = sB[2304+rn+4+tg];
                mma16816(D[nt], a0h,a1h,a2h,a3h, b0h,b1h);
                mma16816(D[nt], a0h,a1h,a2h,a3h, b0l,b1l);
                mma16816(D[nt], a0l,a1l,a2l,a3l, b0h,b1h);
            }
        }
    }

    const int r0 = m0 + 16*w + g, r1 = r0 + 8;
    #pragma unroll
    for (int nt = 0; nt < 8; nt++) {
        int c = n0 + nt*8 + tg*2;
        float2 bi = *(const float2*)(bias + c);
        *(float2*)(out + (size_t)r0 * N + c) = make_float2(D[nt][0]+bi.x, D[nt][1]+bi.y);
        *(float2*)(out + (size_t)r1 * N + c) = make_float2(D[nt][2]+bi.x, D[nt][3]+bi.y);
    }
}

// ============================================================================
// Persistent bidirectional GRU, tensor cores, weights resident in smem.
//   128 blocks x 128 thr, 1 block/SM. dir=bid>>6, 16 hidden cols per block.
//   smem: sWh[48*512] sWl[48*512] (XOR-swizzled) + sH[2buf][2split][64*32].
// ============================================================================
__global__ void __launch_bounds__(128) gru_mma(
    const float* __restrict__ wh_f, const float* __restrict__ wh_b,
    const float* __restrict__ bh_f, const float* __restrict__ bh_b)
{
    extern __shared__ uint32_t smem[];
    uint32_t* sWh = smem;            // 24576 words
    uint32_t* sWl = smem + 24576;    // 24576
    uint32_t* sH  = smem + 49152;    // 8192: [buf*4096 + split*2048 + row*32 + w]

    const int tid = threadIdx.x, w = tid >> 5, lane = tid & 31;
    const int g = lane >> 2, tg = lane & 3;
    const int dir = blockIdx.x >> 6;
    const int j0 = (blockIdx.x & 63) * 16;

    const float* wh = dir ? wh_b : wh_f;
    const float* bh = dir ? bh_b : bh_f;
    const float* xw = dir ? g_xw_b : g_xw_f;
    uint32_t* Hh = dir ? g_hb_h : g_hf_h;
    uint32_t* Hl = dir ? g_hb_l : g_hf_l;

    // preload + split weights: virtual rows 0..47 (16 r, 16 z, 16 n)
    for (int i = tid; i < 48 * 512; i += 128) {
        int vr = i >> 9, wd = i & 511;
        int grow = (vr >> 4) * Hv + j0 + (vr & 15);
        float2 v = *(const float2*)(wh + (size_t)grow * Hv + wd * 2);
        uint32_t wh_, wl_; split2(v.x, v.y, wh_, wl_);
        int ad = vr * 512 + (wd ^ ((vr & 7) << 2));
        sWh[ad] = wh_; sWl[ad] = wl_;
    }
    __syncthreads();

    for (int s = 0; s < Tv; s++) {
        const int t = dir ? (Tv - 1 - s) : s;
        const int tp = dir ? t + 1 : t - 1;

        float D[6][4] = {};

        if (s) {
            grid_bar(dir, 64);
            const uint32_t* ghh = Hh + (size_t)tp * (64*512);
            const uint32_t* ghl = Hl + (size_t)tp * (64*512);
            auto load_stage = [&](int st, int bb) {
                int kw0 = st * 32;
                #pragma unroll
                for (int q = 0; q < 4; q++) {
                    int idx = tid + 128 * q;
                    int row = idx >> 3, seg = idx & 7;
                    int sad = bb * 4096 + row * 32 + ((seg * 4) ^ ((row & 7) << 2));
                    *(uint4*)&sH[sad]        = *(const uint4*)(ghh + (size_t)row*512 + kw0 + seg*4);
                    *(uint4*)&sH[sad + 2048] = *(const uint4*)(ghl + (size_t)row*512 + kw0 + seg*4);
                }
            };
            load_stage(0, 0);
            #pragma unroll 1
            for (int st = 0; st < 16; st++) {
                __syncthreads();
                if (st < 15) load_stage(st + 1, (st + 1) & 1);
                const uint32_t* hb_ = sH + (st & 1) * 4096;
                const int sza = (g & 7) << 2;
                #pragma unroll
                for (int ks = 0; ks < 4; ks++) {
                    int r0 = (16*w + g) * 32, r1 = (16*w + g + 8) * 32;
                    int w0 = (ks*8 + tg) ^ sza, w1 = (ks*8 + 4 + tg) ^ sza;
                    uint32_t a0h = hb_[r0+w0], a1h = hb_[r1+w0];
                    uint32_t a2h = hb_[r0+w1], a3h = hb_[r1+w1];
                    uint32_t a0l = hb_[2048+r0+w0], a1l = hb_[2048+r1+w0];
                    uint32_t a2l = hb_[2048+r0+w1], a3l = hb_[2048+r1+w1];
                    #pragma unroll
                    for (int nt = 0; nt < 6; nt++) {
                        int vr = nt*8 + g;
                        int wb0 = vr*512 + ((st*32 + ks*8 + tg) ^ ((vr & 7) << 2));
                        int wb1 = vr*512 + ((st*32 + ks*8 + 4 + tg) ^ ((vr & 7) << 2));
                        uint32_t b0h = sWh[wb0], b1h = sWh[wb1];
                        uint32_t b0l = sWl[wb0], b1l = sWl[wb1];
                        mma16816(D[nt], a0h,a1h,a2h,a3h, b0h,b1h);
                        mma16816(D[nt], a0h,a1h,a2h,a3h, b0l,b1l);
                        mma16816(D[nt], a0l,a1l,a2l,a3l, b0h,b1h);
                    }
                }
            }
        }

        // epilogue: gates + h update + split store
        const float* xwt = xw + (size_t)t * 64 * G3;
        uint32_t* oh = Hh + (size_t)t * (64*512);
        uint32_t* ol = Hl + (size_t)t * (64*512);
        const uint32_t* ph = Hh + (size_t)(s ? tp : t) * (64*512);
        const uint32_t* pl = Hl + (size_t)(s ? tp : t) * (64*512);
        #pragma unroll
        for (int cg = 0; cg < 2; cg++) {
            int j = j0 + cg*8 + tg*2;
            float2 br_ = *(const float2*)(bh + j);
            float2 bz_ = *(const float2*)(bh + Hv + j);
            float2 bn_ = *(const float2*)(bh + 2*Hv + j);
            #pragma unroll
            for (int rw = 0; rw < 2; rw++) {
                int b = 16*w + g + 8*rw;
                const float* xr = xwt + (size_t)b * G3;
                float2 xrv = *(const float2*)(xr + j);
                float2 xzv = *(const float2*)(xr + Hv + j);
                float2 xnv = *(const float2*)(xr + 2*Hv + j);
                float hp0 = 0.f, hp1 = 0.f;
                if (s) {
                    uint32_t hw_ = ph[(size_t)b*512 + (j>>1)];
                    uint32_t lw_ = pl[(size_t)b*512 + (j>>1)];
                    hp0 = lo16f(hw_) + lo16f(lw_);
                    hp1 = hi16f(hw_) + hi16f(lw_);
                }
                float r0 = sigmoidf_(xrv.x + D[cg][rw*2+0] + br_.x);
                float r1 = sigmoidf_(xrv.y + D[cg][rw*2+1] + br_.y);
                float z0 = sigmoidf_(xzv.x + D[2+cg][rw*2+0] + bz_.x);
                float z1 = sigmoidf_(xzv.y + D[2+cg][rw*2+1] + bz_.y);
                float n0 = tanhf(xnv.x + r0 * (D[4+cg][rw*2+0] + bn_.x));
                float n1 = tanhf(xnv.y + r1 * (D[4+cg][rw*2+1] + bn_.y));
                float h0 = (1.f - z0) * n0 + z0 * hp0;
                float h1 = (1.f - z1) * n1 + z1 * hp1;
                uint32_t sh_, sl_; split2(h0, h1, sh_, sl_);
                oh[(size_t)b*512 + (j>>1)] = sh_;
                ol[(size_t)b*512 + (j>>1)] = sl_;
            }
        }
    }
}

// ============================================================================
// attention: att[t,b] = sigmoid(3*(hf.w[0:H] + hb.w[H:2H] + b))
// ============================================================================
__global__ void att_kernel(const float* __restrict__ fcw, const float* __restrict__ fcb,
                           float* __restrict__ out_att)
{
    const int t = blockIdx.x;
    const int w = threadIdx.x >> 5, lane = threadIdx.x & 31;
    for (int rep = 0; rep < 8; rep++) {
        int b = w + rep * 8;
        size_t o = (size_t)(t * 64 + b) * 512;
        float acc = 0.0f;
        for (int k = lane; k < 512; k += 32) {
            uint32_t hw = g_hf_h[o + k], lw = g_hf_l[o + k];
            float2 wv = *(const float2*)(fcw + 2 * k);
            acc += (lo16f(hw) + lo16f(lw)) * wv.x + (hi16f(hw) + hi16f(lw)) * wv.y;
            hw = g_hb_h[o + k]; lw = g_hb_l[o + k];
            wv = *(const float2*)(fcw + Hv + 2 * k);
            acc += (lo16f(hw) + lo16f(lw)) * wv.x + (hi16f(hw) + hi16f(lw)) * wv.y;
        }
        #pragma unroll
        for (int of = 16; of; of >>= 1) acc += __shfl_xor_sync(0xffffffffu, acc, of);
        if (lane == 0) {
            float a = sigmoidf_(3.0f * (acc + fcb[0]));
            g_att[t * 64 + b] = a;
            out_att[(size_t)b * Tv + t] = a;
        }
    }
}

// ============================================================================
// Persistent TAGM, tensor cores: 128 blocks x 128 thr, 8 cols/block.
//   smem: sWh/sWl[24*512] + sH[2][2][64*32]  (131072 B)
// ============================================================================
__global__ void __launch_bounds__(128) tagm_mma(
    const float* __restrict__ wzr, const float* __restrict__ bzr,
    const float* __restrict__ wt,  const float* __restrict__ bt)
{
    extern __shared__ uint32_t smem[];
    uint32_t* sWh = smem;            // 12288 words
    uint32_t* sWl = smem + 12288;    // 12288
    uint32_t* sH  = smem + 24576;    // 8192

    const int tid = threadIdx.x, w = tid >> 5, lane = tid & 31;
    const int g = lane >> 2, tg = lane & 3;
    const int j0 = blockIdx.x * 8;

    // preload weights: rows 0..7 r, 8..15 z, 16..23 t-hat
    for (int i = tid; i < 24 * 512; i += 128) {
        int vr = i >> 9, wd = i & 511;
        int gate = vr >> 3, jj = vr & 7;
        const float* src = (gate < 2) ? (wzr + (size_t)(gate * Hv + j0 + jj) * Hv)
                                      : (wt + (size_t)(j0 + jj) * Hv);
        float2 v = *(const float2*)(src + wd * 2);
        uint32_t wh_, wl_; split2(v.x, v.y, wh_, wl_);
        int ad = vr * 512 + (wd ^ ((vr & 7) << 2));
        sWh[ad] = wh_; sWl[ad] = wl_;
    }
    __syncthreads();

    const int j = j0 + tg * 2;
    for (int s = 0; s < Tv; s++) {
        float D[3][4] = {};

        if (s) {
            grid_bar(2, 128);
            const uint32_t* ghh = g_ht_h + (size_t)(s - 1) * (64*512);
            const uint32_t* ghl = g_ht_l + (size_t)(s - 1) * (64*512);
            auto load_stage = [&](int st, int bb) {
                int kw0 = st * 32;
                #pragma unroll
                for (int q = 0; q < 4; q++) {
                    int idx = tid + 128 * q;
                    int row = idx >> 3, seg = idx & 7;
                    int sad = bb * 4096 + row * 32 + ((seg * 4) ^ ((row & 7) << 2));
                    *(uint4*)&sH[sad]        = *(const uint4*)(ghh + (size_t)row*512 + kw0 + seg*4);
                    *(uint4*)&sH[sad + 2048] = *(const uint4*)(ghl + (size_t)row*512 + kw0 + seg*4);
                }
            };
            load_stage(0, 0);
            #pragma unroll 1
            for (int st = 0; st < 16; st++) {
                __syncthreads();
                if (st < 15) load_stage(st + 1, (st + 1) & 1);
                const uint32_t* hb_ = sH + (st & 1) * 4096;
                const int sza = (g & 7) << 2;
                #pragma unroll
                for (int ks = 0; ks < 4; ks++) {
                    int r0 = (16*w + g) * 32, r1 = (16*w + g + 8) * 32;
                    int w0 = (ks*8 + tg) ^ sza, w1 = (ks*8 + 4 + tg) ^ sza;
                    uint32_t a0h = hb_[r0+w0], a1h = hb_[r1+w0];
                    uint32_t a2h = hb_[r0+w1], a3h = hb_[r1+w1];
                    uint32_t a0l = hb_[2048+r0+w0], a1l = hb_[2048+r1+w0];
                    uint32_t a2l = hb_[2048+r0+w1], a3l = hb_[2048+r1+w1];
                    #pragma unroll
                    for (int nt = 0; nt < 3; nt++) {
                        int vr = nt*8 + g;
                        int wb0 = vr*512 + ((st*32 + ks*8 + tg) ^ ((vr & 7) << 2));
                        int wb1 = vr*512 + ((st*32 + ks*8 + 4 + tg) ^ ((vr & 7) << 2));
                        uint32_t b0h = sWh[wb0], b1h = sWh[wb1];
                        uint32_t b0l = sWl[wb0], b1l = sWl[wb1];
                        mma16816(D[nt], a0h,a1h,a2h,a3h, b0h,b1h);
                        mma16816(D[nt], a0h,a1h,a2h,a3h, b0l,b1l);
                        mma16816(D[nt], a0l,a1l,a2l,a3l, b0h,b1h);
                    }
                }
            }
        }

        // epilogue
        uint32_t* oh = g_ht_h + (size_t)s * (64*512);
        uint32_t* ol = g_ht_l + (size_t)s * (64*512);
        const uint32_t* ph = g_ht_h + (size_t)(s ? s - 1 : 0) * (64*512);
        const uint32_t* pl = g_ht_l + (size_t)(s ? s - 1 : 0) * (64*512);
        float2 br_ = *(const float2*)(bzr + j);
        float2 bz_ = *(const float2*)(bzr + Hv + j);
        float2 bt_ = *(const float2*)(bt + j);
        #pragma unroll
        for (int rw = 0; rw < 2; rw++) {
            int b = 16*w + g + 8*rw;
            float a = g_att[s * 64 + b];
            float2 xrv = *(const float2*)(g_xzr + (size_t)(s*64 + b) * G2 + j);
            float2 xzv = *(const float2*)(g_xzr + (size_t)(s*64 + b) * G2 + Hv + j);
            float2 xtv = *(const float2*)(g_xt  + (size_t)(s*64 + b) * Hv + j);
            float hp0 = 0.f, hp1 = 0.f;
            if (s) {
                uint32_t hw_ = ph[(size_t)b*512 + (j>>1)];
                uint32_t lw_ = pl[(size_t)b*512 + (j>>1)];
                hp0 = lo16f(hw_) + lo16f(lw_);
                hp1 = hi16f(hw_) + hi16f(lw_);
            }
            float r0 = sigmoidf_(xrv.x + D[0][rw*2+0] + br_.x);
            float r1 = sigmoidf_(xrv.y + D[0][rw*2+1] + br_.y);
            float z0 = sigmoidf_(xzv.x + D[1][rw*2+0] + bz_.x);
            float z1 = sigmoidf_(xzv.y + D[1][rw*2+1] + bz_.y);
            float t0 = tanhf(xtv.x + r0 * (D[2][rw*2+0] + bt_.x));
            float t1 = tanhf(xtv.y + r1 * (D[2][rw*2+1] + bt_.y));
            float h0 = a * (z0 * t0 + (1.f - z0) * hp0);
            float h1 = a * (z1 * t1 + (1.f - z1) * hp1);
            uint32_t sh_, sl_; split2(h0, h1, sh_, sl_);
            oh[(size_t)b*512 + (j>>1)] = sh_;
            ol[(size_t)b*512 + (j>>1)] = sl_;
        }
    }
}

// ============================================================================
// fc0
// ============================================================================
__global__ void fc0_kernel(const float* __restrict__ w, const float* __restrict__ bias,
                           float* __restrict__ out)
{
    const int b = blockIdx.x;
    const int wp = threadIdx.x >> 5, lane = threadIdx.x & 31;
    size_t o = (size_t)((Tv - 1) * 64 + b) * 512;
    for (int c = wp; c < Cv; c += 8) {
        float acc = 0.0f;
        for (int k = lane; k < 512; k += 32) {
            uint32_t hw = g_ht_h[o + k], lw = g_ht_l[o + k];
            float2 wv = *(const float2*)(w + (size_t)c * Hv + 2 * k);
            acc += (lo16f(hw) + lo16f(lw)) * wv.x + (hi16f(hw) + hi16f(lw)) * wv.y;
        }
        #pragma unroll
        for (int of = 16; of; of >>= 1) acc += __shfl_xor_sync(0xffffffffu, acc, of);
        if (lane == 0) out[(size_t)b * Cv + c] = acc + bias[c];
    }
}

// ============================================================================
extern "C" void kernel_launch(void* const* d_in, const int* in_sizes, int n_in,
                              void* d_out, int out_size)
{
    const float* x        = (const float*)d_in[0];
    const float* att_wi_f = (const float*)d_in[1];
    const float* att_wh_f = (const float*)d_in[2];
    const float* att_bi_f = (const float*)d_in[3];
    const float* att_bh_f = (const float*)d_in[4];
    const float* att_wi_b = (const float*)d_in[5];
    const float* att_wh_b = (const float*)d_in[6];
    const float* att_bi_b = (const float*)d_in[7];
    const float* att_bh_b = (const float*)d_in[8];
    const float* att_fc_w = (const float*)d_in[9];
    const float* att_fc_b = (const float*)d_in[10];
    const float* w_i2h_zr = (const float*)d_in[11];
    const float* b_i2h_zr = (const float*)d_in[12];
    const float* w_h2h_zr = (const float*)d_in[13];
    const float* b_h2h_zr = (const float*)d_in[14];
    const float* w_i2h_t  = (const float*)d_in[15];
    const float* b_i2h_t  = (const float*)d_in[16];
    const float* w_h2h_t  = (const float*)d_in[17];
    const float* b_h2h_t  = (const float*)d_in[18];
    const float* fc0_w    = (const float*)d_in[19];
    const float* fc0_b    = (const float*)d_in[20];

    float* out     = (float*)d_out;
    float* out_att = out + Bv * Cv;

    cudaFuncSetAttribute(gru_mma,  cudaFuncAttributeMaxDynamicSharedMemorySize, 229376);
    cudaFuncSetAttribute(tagm_mma, cudaFuncAttributeMaxDynamicSharedMemorySize, 131072);

    float *p_xwf, *p_xwb, *p_xzr, *p_xt;
    cudaGetSymbolAddress((void**)&p_xwf, g_xw_f);
    cudaGetSymbolAddress((void**)&p_xwb, g_xw_b);
    cudaGetSymbolAddress((void**)&p_xzr, g_xzr);
    cudaGetSymbolAddress((void**)&p_xt,  g_xt);
    uint32_t *p_xh, *p_xl, *p_fh, *p_fl, *p_bh, *p_bl, *p_zh, *p_zl, *p_th, *p_tl;
    cudaGetSymbolAddress((void**)&p_xh, g_xh);     cudaGetSymbolAddress((void**)&p_xl, g_xl);
    cudaGetSymbolAddress((void**)&p_fh, g_wif_h);  cudaGetSymbolAddress((void**)&p_fl, g_wif_l);
    cudaGetSymbolAddress((void**)&p_bh, g_wib_h);  cudaGetSymbolAddress((void**)&p_bl, g_wib_l);
    cudaGetSymbolAddress((void**)&p_zh, g_wizr_h); cudaGetSymbolAddress((void**)&p_zl, g_wizr_l);
    cudaGetSymbolAddress((void**)&p_th, g_wit_h);  cudaGetSymbolAddress((void**)&p_tl, g_wit_l);

    // 0) conversions to split-bf16
    conv_x<<<32768, 256>>>(x);
    conv_w<<<3072, 256>>>(att_wi_f, p_fh, p_fl);
    conv_w<<<3072, 256>>>(att_wi_b, p_bh, p_bl);
    conv_w<<<2048, 256>>>(w_i2h_zr, p_zh, p_zl);
    conv_w<<<1024, 256>>>(w_i2h_t,  p_th, p_tl);

    // 1) input projections (tensor cores)
    proj_mma<<<dim3(48, 512), 128>>>(p_xh, p_xl, p_fh, p_fl, att_bi_f, p_xwf, G3);
    proj_mma<<<dim3(48, 512), 128>>>(p_xh, p_xl, p_bh, p_bl, att_bi_b, p_xwb, G3);
    proj_mma<<<dim3(32, 512), 128>>>(p_xh, p_xl, p_zh, p_zl, b_i2h_zr, p_xzr, G2);
    proj_mma<<<dim3(16, 512), 128>>>(p_xh, p_xl, p_th, p_tl, b_i2h_t,  p_xt,  Hv);

    // 2) bidirectional GRU — persistent, tensor cores
    gru_mma<<<128, 128, 229376>>>(att_wh_f, att_wh_b, att_bh_f, att_bh_b);

    // 3) attention gate
    att_kernel<<<Tv, 256>>>(att_fc_w, att_fc_b, out_att);

    // 4) TAGM — persistent, tensor cores
    tagm_mma<<<128, 128, 131072>>>(w_h2h_zr, b_h2h_zr, w_h2h_t, b_h2h_t);

    // 5) final projection
    fc0_kernel<<<Bv, 256>>>(fc0_w, fc0_b, out);
}

// round 7
// speedup vs baseline: 1.6469x; 1.1133x over previous
#include <cuda_runtime.h>
#include <cuda_bf16.h>
#include <math.h>
#include <stdint.h>

#define Bv 64
#define Tv 512
#define Iv 512
#define Hv 1024
#define Cv 128
#define G3 (3*Hv)
#define G2 (2*Hv)

// ---------------- static device scratch ----------------
__device__ float g_xw_f[(size_t)Tv*Bv*G3];
__device__ float g_xw_b[(size_t)Tv*Bv*G3];
__device__ float g_xzr [(size_t)Tv*Bv*G2];
__device__ float g_xt  [(size_t)Tv*Bv*Hv];
__device__ float g_att [Tv*Bv];

// packed bf16-pair words (word w = elems 2w (lo16), 2w+1 (hi16))
__device__ uint32_t g_xh[(size_t)32768*256], g_xl[(size_t)32768*256];
__device__ uint32_t g_wif_h[(size_t)3072*256],  g_wif_l[(size_t)3072*256];
__device__ uint32_t g_wib_h[(size_t)3072*256],  g_wib_l[(size_t)3072*256];
__device__ uint32_t g_wizr_h[(size_t)2048*256], g_wizr_l[(size_t)2048*256];
__device__ uint32_t g_wit_h[(size_t)1024*256],  g_wit_l[(size_t)1024*256];
// hidden-state histories, split-bf16 words [t][b][512]
__device__ uint32_t g_hf_h[(size_t)Tv*Bv*512], g_hf_l[(size_t)Tv*Bv*512];
__device__ uint32_t g_hb_h[(size_t)Tv*Bv*512], g_hb_l[(size_t)Tv*Bv*512];
__device__ uint32_t g_ht_h[(size_t)Tv*Bv*512], g_ht_l[(size_t)Tv*Bv*512];

__device__ unsigned g_bar_cnt[3*32];
__device__ unsigned g_bar_gen[3*32];

__device__ __forceinline__ float sigmoidf_(float x) { return 1.0f / (1.0f + expf(-x)); }
__device__ __forceinline__ float lo16f(uint32_t w) { return __uint_as_float(w << 16); }
__device__ __forceinline__ float hi16f(uint32_t w) { return __uint_as_float(w & 0xffff0000u); }
__device__ __forceinline__ uint32_t bfbits(float x) {
    __nv_bfloat16 h = __float2bfloat16(x);
    return (uint32_t)*reinterpret_cast<unsigned short*>(&h);
}
__device__ __forceinline__ void split2(float x0, float x1, uint32_t& wh, uint32_t& wl) {
    uint32_t h0 = bfbits(x0), h1 = bfbits(x1);
    float r0 = x0 - __uint_as_float(h0 << 16);
    float r1 = x1 - __uint_as_float(h1 << 16);
    wh = h0 | (h1 << 16);
    wl = bfbits(r0) | (bfbits(r1) << 16);
}

__device__ __forceinline__ void mma16816(float* d,
    uint32_t a0, uint32_t a1, uint32_t a2, uint32_t a3, uint32_t b0, uint32_t b1) {
    asm volatile(
        "mma.sync.aligned.m16n8k16.row.col.f32.bf16.bf16.f32 "
        "{%0,%1,%2,%3},{%4,%5,%6,%7},{%8,%9},{%0,%1,%2,%3};"
        : "+f"(d[0]), "+f"(d[1]), "+f"(d[2]), "+f"(d[3])
        : "r"(a0), "r"(a1), "r"(a2), "r"(a3), "r"(b0), "r"(b1));
}

__device__ __forceinline__ void grid_bar(int grp, unsigned nb) {
    volatile unsigned* gen = (volatile unsigned*)&g_bar_gen[grp*32];
    unsigned* cnt = &g_bar_cnt[grp*32];
    __threadfence();
    __syncthreads();
    if (threadIdx.x == 0) {
        unsigned g = *gen;
        if (atomicAdd(cnt, 1u) == nb - 1) {
            atomicExch(cnt, 0u);
            __threadfence();
            *gen = g + 1;
        } else {
            while (*gen == g) __nanosleep(64);
            __threadfence();
        }
    }
    __syncthreads();
}

// ============================================================================
// converters
// ============================================================================
__global__ void conv_x(const float* __restrict__ x) {
    int r = blockIdx.x, wi = threadIdx.x;          // r = t*64+b
    int b = r & 63, t = r >> 6;
    float2 v = ((const float2*)x)[((size_t)b * Tv + t) * 256 + wi];
    uint32_t wh, wl; split2(v.x, v.y, wh, wl);
    g_xh[(size_t)r * 256 + wi] = wh;
    g_xl[(size_t)r * 256 + wi] = wl;
}
__global__ void conv_w(const float* __restrict__ src,
                       uint32_t* __restrict__ hi, uint32_t* __restrict__ lo) {
    size_t i = (size_t)blockIdx.x * 256 + threadIdx.x;
    float2 v = ((const float2*)src)[i];
    uint32_t wh, wl; split2(v.x, v.y, wh, wl);
    hi[i] = wh; lo[i] = wl;
}

// ============================================================================
// proj via bf16-split mma: out[r,n] = x[r,:].W[n,:] + bias[n]; tile 64x64xK512
// ============================================================================
__global__ void __launch_bounds__(128) proj_mma(
    const uint32_t* __restrict__ Ah, const uint32_t* __restrict__ Al,
    const uint32_t* __restrict__ Wh, const uint32_t* __restrict__ Wl,
    const float* __restrict__ bias, float* __restrict__ out, int N)
{
    __shared__ uint32_t sA[2*64*36], sB[2*64*36];   // hi at 0, lo at +2304
    const int tid = threadIdx.x, w = tid >> 5, lane = tid & 31;
    const int g = lane >> 2, tg = lane & 3;
    const int m0 = blockIdx.y * 64, n0 = blockIdx.x * 64;

    float D[8][4] = {};

    #pragma unroll 1
    for (int st = 0; st < 8; st++) {
        const int kw0 = st * 32;
        __syncthreads();
        #pragma unroll
        for (int q = 0; q < 4; q++) {
            int idx = tid + 128 * q;
            int row = idx >> 3, seg = idx & 7;
            *(uint4*)&sA[row*36 + seg*4]        = *(const uint4*)(Ah + (size_t)(m0+row)*256 + kw0 + seg*4);
            *(uint4*)&sA[2304 + row*36 + seg*4] = *(const uint4*)(Al + (size_t)(m0+row)*256 + kw0 + seg*4);
            *(uint4*)&sB[row*36 + seg*4]        = *(const uint4*)(Wh + (size_t)(n0+row)*256 + kw0 + seg*4);
            *(uint4*)&sB[2304 + row*36 + seg*4] = *(const uint4*)(Wl + (size_t)(n0+row)*256 + kw0 + seg*4);
        }
        __syncthreads();
        #pragma unroll
        for (int ks = 0; ks < 4; ks++) {
            int ra = (16*w + g) * 36 + ks * 8, rb = ra + 8*36;
            uint32_t a0h = sA[ra+tg],      a2h = sA[ra+4+tg];
            uint32_t a1h = sA[rb+tg],      a3h = sA[rb+4+tg];
            uint32_t a0l = sA[2304+ra+tg], a2l = sA[2304+ra+4+tg];
            uint32_t a1l = sA[2304+rb+tg], a3l = sA[2304+rb+4+tg];
            #pragma unroll
            for (int nt = 0; nt < 8; nt++) {
                int rn = (nt*8 + g) * 36 + ks * 8;
                uint32_t b0h = sB[rn+tg],      b1h = sB[rn+4+tg];
                uint32_t b0l = sB[2304+rn+tg], b1l = sB[2304+rn+4+tg];
                mma16816(D[nt], a0h,a1h,a2h,a3h, b0h,b1h);
                mma16816(D[nt], a0h,a1h,a2h,a3h, b0l,b1l);
                mma16816(D[nt], a0l,a1l,a2l,a3l, b0h,b1h);
            }
        }
    }

    const int r0 = m0 + 16*w + g, r1 = r0 + 8;
    #pragma unroll
    for (int nt = 0; nt < 8; nt++) {
        int c = n0 + nt*8 + tg*2;
        float2 bi = *(const float2*)(bias + c);
        *(float2*)(out + (size_t)r0 * N + c) = make_float2(D[nt][0]+bi.x, D[nt][1]+bi.y);
        *(float2*)(out + (size_t)r1 * N + c) = make_float2(D[nt][2]+bi.x, D[nt][3]+bi.y);
    }
}

// ============================================================================
// Persistent bidirectional GRU, tensor cores, 256 threads (2 warps/SMSP).
//   128 blocks. dir = bid>>6, 16 hidden cols per block.
//   warp: mt = w&3 (16 batch rows), ch = w>>2 (8 of the 16 cols).
//   smem: sWh/sWl[48*512] (swizzled) + sH[2buf][2split][64*32].
// ============================================================================
__global__ void __launch_bounds__(256) gru_mma(
    const float* __restrict__ wh_f, const float* __restrict__ wh_b,
    const float* __restrict__ bh_f, const float* __restrict__ bh_b)
{
    extern __shared__ uint32_t smem[];
    uint32_t* sWh = smem;            // 24576 words
    uint32_t* sWl = smem + 24576;    // 24576
    uint32_t* sH  = smem + 49152;    // 8192

    const int tid = threadIdx.x, w = tid >> 5, lane = tid & 31;
    const int g = lane >> 2, tg = lane & 3;
    const int mt = w & 3, ch = w >> 2;
    const int dir = blockIdx.x >> 6;
    const int j0 = (blockIdx.x & 63) * 16;

    const float* wh = dir ? wh_b : wh_f;
    const float* bh = dir ? bh_b : bh_f;
    const float* xw = dir ? g_xw_b : g_xw_f;
    uint32_t* Hh = dir ? g_hb_h : g_hf_h;
    uint32_t* Hl = dir ? g_hb_l : g_hf_l;

    // preload + split weights: virtual rows 0..47 (16 r, 16 z, 16 n)
    for (int i = tid; i < 48 * 512; i += 256) {
        int vr = i >> 9, wd = i & 511;
        int grow = (vr >> 4) * Hv + j0 + (vr & 15);
        float2 v = *(const float2*)(wh + (size_t)grow * Hv + wd * 2);
        uint32_t wh_, wl_; split2(v.x, v.y, wh_, wl_);
        int ad = vr * 512 + (wd ^ ((vr & 7) << 2));
        sWh[ad] = wh_; sWl[ad] = wl_;
    }
    __syncthreads();

    // per-thread fixed columns & biases (hoisted)
    const int j = j0 + ch * 8 + tg * 2;
    const float2 br_ = *(const float2*)(bh + j);
    const float2 bz_ = *(const float2*)(bh + Hv + j);
    const float2 bn_ = *(const float2*)(bh + 2*Hv + j);

    for (int s = 0; s < Tv; s++) {
        const int t = dir ? (Tv - 1 - s) : s;
        const int tp = dir ? t + 1 : t - 1;

        float D[3][4] = {};

        if (s) {
            grid_bar(dir, 64);
            const uint32_t* ghh = Hh + (size_t)tp * (64*512);
            const uint32_t* ghl = Hl + (size_t)tp * (64*512);
            auto load_stage = [&](int st, int bb) {
                int kw0 = st * 32;
                #pragma unroll
                for (int q = 0; q < 2; q++) {
                    int idx = tid + 256 * q;
                    int row = idx >> 3, seg = idx & 7;
                    int sad = bb * 4096 + row * 32 + ((seg * 4) ^ ((row & 7) << 2));
                    *(uint4*)&sH[sad]        = *(const uint4*)(ghh + (size_t)row*512 + kw0 + seg*4);
                    *(uint4*)&sH[sad + 2048] = *(const uint4*)(ghl + (size_t)row*512 + kw0 + seg*4);
                }
            };
            load_stage(0, 0);
            const int r0 = (16*mt + g) * 32, r1 = (16*mt + 8 + g) * 32;
            const int sza = g << 2;
            #pragma unroll 1
            for (int st = 0; st < 16; st++) {
                __syncthreads();
                if (st < 15) load_stage(st + 1, (st + 1) & 1);
                const uint32_t* hb_ = sH + (st & 1) * 4096;
                #pragma unroll
                for (int ks = 0; ks < 4; ks++) {
                    int w0 = (ks*8 + tg) ^ sza, w1 = (ks*8 + 4 + tg) ^ sza;
                    uint32_t a0h = hb_[r0+w0], a1h = hb_[r1+w0];
                    uint32_t a2h = hb_[r0+w1], a3h = hb_[r1+w1];
                    uint32_t a0l = hb_[2048+r0+w0], a1l = hb_[2048+r1+w0];
                    uint32_t a2l = hb_[2048+r0+w1], a3l = hb_[2048+r1+w1];
                    #pragma unroll
                    for (int gate = 0; gate < 3; gate++) {
                        int vr = gate*16 + ch*8 + g;
                        int wb0 = vr*512 + ((st*32 + ks*8 + tg) ^ ((vr & 7) << 2));
                        int wb1 = vr*512 + ((st*32 + ks*8 + 4 + tg) ^ ((vr & 7) << 2));
                        uint32_t b0h = sWh[wb0], b1h = sWh[wb1];
                        uint32_t b0l = sWl[wb0], b1l = sWl[wb1];
                        mma16816(D[gate], a0h,a1h,a2h,a3h, b0h,b1h);
                        mma16816(D[gate], a0h,a1h,a2h,a3h, b0l,b1l);
                        mma16816(D[gate], a0l,a1l,a2l,a3l, b0h,b1h);
                    }
                }
            }
        }

        // epilogue: gates + h update + split store (warp-local, all gates present)
        const float* xwt = xw + (size_t)t * 64 * G3;
        uint32_t* oh = Hh + (size_t)t * (64*512);
        uint32_t* ol = Hl + (size_t)t * (64*512);
        const uint32_t* ph = Hh + (size_t)(s ? tp : t) * (64*512);
        const uint32_t* pl = Hl + (size_t)(s ? tp : t) * (64*512);
        #pragma unroll
        for (int rw = 0; rw < 2; rw++) {
            int b = 16*mt + g + 8*rw;
            const float* xr = xwt + (size_t)b * G3;
            float2 xrv = *(const float2*)(xr + j);
            float2 xzv = *(const float2*)(xr + Hv + j);
            float2 xnv = *(const float2*)(xr + 2*Hv + j);
            float hp0 = 0.f, hp1 = 0.f;
            if (s) {
                uint32_t hw_ = ph[(size_t)b*512 + (j>>1)];
                uint32_t lw_ = pl[(size_t)b*512 + (j>>1)];
                hp0 = lo16f(hw_) + lo16f(lw_);
                hp1 = hi16f(hw_) + hi16f(lw_);
            }
            float r0 = sigmoidf_(xrv.x + D[0][rw*2+0] + br_.x);
            float r1 = sigmoidf_(xrv.y + D[0][rw*2+1] + br_.y);
            float z0 = sigmoidf_(xzv.x + D[1][rw*2+0] + bz_.x);
            float z1 = sigmoidf_(xzv.y + D[1][rw*2+1] + bz_.y);
            float n0 = tanhf(xnv.x + r0 * (D[2][rw*2+0] + bn_.x));
            float n1 = tanhf(xnv.y + r1 * (D[2][rw*2+1] + bn_.y));
            float h0 = (1.f - z0) * n0 + z0 * hp0;
            float h1 = (1.f - z1) * n1 + z1 * hp1;
            uint32_t sh_, sl_; split2(h0, h1, sh_, sl_);
            oh[(size_t)b*512 + (j>>1)] = sh_;
            ol[(size_t)b*512 + (j>>1)] = sl_;
        }
    }
}

// ============================================================================
// attention: att[t,b] = sigmoid(3*(hf.w[0:H] + hb.w[H:2H] + b))
// ============================================================================
__global__ void att_kernel(const float* __restrict__ fcw, const float* __restrict__ fcb,
                           float* __restrict__ out_att)
{
    const int t = blockIdx.x;
    const int w = threadIdx.x >> 5, lane = threadIdx.x & 31;
    for (int rep = 0; rep < 8; rep++) {
        int b = w + rep * 8;
        size_t o = (size_t)(t * 64 + b) * 512;
        float acc = 0.0f;
        for (int k = lane; k < 512; k += 32) {
            uint32_t hw = g_hf_h[o + k], lw = g_hf_l[o + k];
            float2 wv = *(const float2*)(fcw + 2 * k);
            acc += (lo16f(hw) + lo16f(lw)) * wv.x + (hi16f(hw) + hi16f(lw)) * wv.y;
            hw = g_hb_h[o + k]; lw = g_hb_l[o + k];
            wv = *(const float2*)(fcw + Hv + 2 * k);
            acc += (lo16f(hw) + lo16f(lw)) * wv.x + (hi16f(hw) + hi16f(lw)) * wv.y;
        }
        #pragma unroll
        for (int of = 16; of; of >>= 1) acc += __shfl_xor_sync(0xffffffffu, acc, of);
        if (lane == 0) {
            float a = sigmoidf_(3.0f * (acc + fcb[0]));
            g_att[t * 64 + b] = a;
            out_att[(size_t)b * Tv + t] = a;
        }
    }
}

// ============================================================================
// Persistent TAGM, tensor cores, 256 threads: 128 blocks, 8 cols/block.
//   warp: mt = w&3 (16 batch rows), kh = w>>2 (2 of the 4 ks per stage).
//   smem: sWh/sWl[24*512] + sH[2][2][64*32] + red[1536]  (137,216 B)
// ============================================================================
__global__ void __launch_bounds__(256) tagm_mma(
    const float* __restrict__ wzr, const float* __restrict__ bzr,
    const float* __restrict__ wt,  const float* __restrict__ bt)
{
    extern __shared__ uint32_t smem[];
    uint32_t* sWh = smem;            // 12288 words
    uint32_t* sWl = smem + 12288;    // 12288
    uint32_t* sH  = smem + 24576;    // 8192
    float*    red = (float*)(smem + 32768);  // 1536 floats

    const int tid = threadIdx.x, w = tid >> 5, lane = tid & 31;
    const int g = lane >> 2, tg = lane & 3;
    const int mt = w & 3, kh = w >> 2;
    const int j0 = blockIdx.x * 8;

    // preload weights: rows 0..7 r, 8..15 z, 16..23 t-hat
    for (int i = tid; i < 24 * 512; i += 256) {
        int vr = i >> 9, wd = i & 511;
        int gate = vr >> 3, jj = vr & 7;
        const float* src = (gate < 2) ? (wzr + (size_t)(gate * Hv + j0 + jj) * Hv)
                                      : (wt + (size_t)(j0 + jj) * Hv);
        float2 v = *(const float2*)(src + wd * 2);
        uint32_t wh_, wl_; split2(v.x, v.y, wh_, wl_);
        int ad = vr * 512 + (wd ^ ((vr & 7) << 2));
        sWh[ad] = wh_; sWl[ad] = wl_;
    }
    __syncthreads();

    const int j = j0 + tg * 2;
    const float2 br_ = *(const float2*)(bzr + j);
    const float2 bz_ = *(const float2*)(bzr + Hv + j);
    const float2 bt_ = *(const float2*)(bt + j);

    for (int s = 0; s < Tv; s++) {
        float D[3][4] = {};

        if (s) {
            grid_bar(2, 128);
            const uint32_t* ghh = g_ht_h + (size_t)(s - 1) * (64*512);
            const uint32_t* ghl = g_ht_l + (size_t)(s - 1) * (64*512);
            auto load_stage = [&](int st, int bb) {
                int kw0 = st * 32;
                #pragma unroll
                for (int q = 0; q < 2; q++) {
                    int idx = tid + 256 * q;
                    int row = idx >> 3, seg = idx & 7;
                    int sad = bb * 4096 + row * 32 + ((seg * 4) ^ ((row & 7) << 2));
                    *(uint4*)&sH[sad]        = *(const uint4*)(ghh + (size_t)row*512 + kw0 + seg*4);
                    *(uint4*)&sH[sad + 2048] = *(const uint4*)(ghl + (size_t)row*512 + kw0 + seg*4);
                }
            };
            load_stage(0, 0);
            const int r0 = (16*mt + g) * 32, r1 = (16*mt + 8 + g) * 32;
            const int sza = g << 2;
            #pragma unroll 1
            for (int st = 0; st < 16; st++) {
                __syncthreads();
                if (st < 15) load_stage(st + 1, (st + 1) & 1);
                const uint32_t* hb_ = sH + (st & 1) * 4096;
                #pragma unroll
                for (int ki = 0; ki < 2; ki++) {
                    int ks = 2 * kh + ki;
                    int w0 = (ks*8 + tg) ^ sza, w1 = (ks*8 + 4 + tg) ^ sza;
                    uint32_t a0h = hb_[r0+w0], a1h = hb_[r1+w0];
                    uint32_t a2h = hb_[r0+w1], a3h = hb_[r1+w1];
                    uint32_t a0l = hb_[2048+r0+w0], a1l = hb_[2048+r1+w0];
                    uint32_t a2l = hb_[2048+r0+w1], a3l = hb_[2048+r1+w1];
                    #pragma unroll
                    for (int gate = 0; gate < 3; gate++) {
                        int vr = gate*8 + g;
                        int wb0 = vr*512 + ((st*32 + ks*8 + tg) ^ (g << 2));
                        int wb1 = vr*512 + ((st*32 + ks*8 + 4 + tg) ^ (g << 2));
                        uint32_t b0h = sWh[wb0], b1h = sWh[wb1];
                        uint32_t b0l = sWl[wb0], b1l = sWl[wb1];
                        mma16816(D[gate], a0h,a1h,a2h,a3h, b0h,b1h);
                        mma16816(D[gate], a0h,a1h,a2h,a3h, b0l,b1l);
                        mma16816(D[gate], a0l,a1l,a2l,a3l, b0h,b1h);
                    }
                }
            }
            // combine k-halves: warps 4..7 publish, warps 0..3 accumulate
            __syncthreads();
            if (kh == 1) {
                float* rp = red + ((w - 4) * 32 + lane) * 12;
                #pragma unroll
                for (int gate = 0; gate < 3; gate++)
                    #pragma unroll
                    for (int e = 0; e < 4; e++) rp[gate*4 + e] = D[gate][e];
            }
            __syncthreads();
            if (kh == 0) {
                const float* rp = red + (w * 32 + lane) * 12;
                #pragma unroll
                for (int gate = 0; gate < 3; gate++)
                    #pragma unroll
                    for (int e = 0; e < 4; e++) D[gate][e] += rp[gate*4 + e];
            }
        }

        // epilogue (warps 0..3 only; each owns 16 rows x 8 cols, all gates)
        if (kh == 0) {
            uint32_t* oh = g_ht_h + (size_t)s * (64*512);
            uint32_t* ol = g_ht_l + (size_t)s * (64*512);
            const uint32_t* ph = g_ht_h + (size_t)(s ? s - 1 : 0) * (64*512);
            const uint32_t* pl = g_ht_l + (size_t)(s ? s - 1 : 0) * (64*512);
            #pragma unroll
            for (int rw = 0; rw < 2; rw++) {
                int b = 16*mt + g + 8*rw;
                float a = g_att[s * 64 + b];
                float2 xrv = *(const float2*)(g_xzr + (size_t)(s*64 + b) * G2 + j);
                float2 xzv = *(const float2*)(g_xzr + (size_t)(s*64 + b) * G2 + Hv + j);
                float2 xtv = *(const float2*)(g_xt  + (size_t)(s*64 + b) * Hv + j);
                float hp0 = 0.f, hp1 = 0.f;
                if (s) {
                    uint32_t hw_ = ph[(size_t)b*512 + (j>>1)];
                    uint32_t lw_ = pl[(size_t)b*512 + (j>>1)];
                    hp0 = lo16f(hw_) + lo16f(lw_);
                    hp1 = hi16f(hw_) + hi16f(lw_);
                }
                float r0 = sigmoidf_(xrv.x + D[0][rw*2+0] + br_.x);
                float r1 = sigmoidf_(xrv.y + D[0][rw*2+1] + br_.y);
                float z0 = sigmoidf_(xzv.x + D[1][rw*2+0] + bz_.x);
                float z1 = sigmoidf_(xzv.y + D[1][rw*2+1] + bz_.y);
                float t0 = tanhf(xtv.x + r0 * (D[2][rw*2+0] + bt_.x));
                float t1 = tanhf(xtv.y + r1 * (D[2][rw*2+1] + bt_.y));
                float h0 = a * (z0 * t0 + (1.f - z0) * hp0);
                float h1 = a * (z1 * t1 + (1.f - z1) * hp1);
                uint32_t sh_, sl_; split2(h0, h1, sh_, sl_);
                oh[(size_t)b*512 + (j>>1)] = sh_;
                ol[(size_t)b*512 + (j>>1)] = sl_;
            }
        }
    }
}

// ============================================================================
// fc0
// ============================================================================
__global__ void fc0_kernel(const float* __restrict__ w, const float* __restrict__ bias,
                           float* __restrict__ out)
{
    const int b = blockIdx.x;
    const int wp = threadIdx.x >> 5, lane = threadIdx.x & 31;
    size_t o = (size_t)((Tv - 1) * 64 + b) * 512;
    for (int c = wp; c < Cv; c += 8) {
        float acc = 0.0f;
        for (int k = lane; k < 512; k += 32) {
            uint32_t hw = g_ht_h[o + k], lw = g_ht_l[o + k];
            float2 wv = *(const float2*)(w + (size_t)c * Hv + 2 * k);
            acc += (lo16f(hw) + lo16f(lw)) * wv.x + (hi16f(hw) + hi16f(lw)) * wv.y;
        }
        #pragma unroll
        for (int of = 16; of; of >>= 1) acc += __shfl_xor_sync(0xffffffffu, acc, of);
        if (lane == 0) out[(size_t)b * Cv + c] = acc + bias[c];
    }
}

// ============================================================================
extern "C" void kernel_launch(void* const* d_in, const int* in_sizes, int n_in,
                              void* d_out, int out_size)
{
    const float* x        = (const float*)d_in[0];
    const float* att_wi_f = (const float*)d_in[1];
    const float* att_wh_f = (const float*)d_in[2];
    const float* att_bi_f = (const float*)d_in[3];
    const float* att_bh_f = (const float*)d_in[4];
    const float* att_wi_b = (const float*)d_in[5];
    const float* att_wh_b = (const float*)d_in[6];
    const float* att_bi_b = (const float*)d_in[7];
    const float* att_bh_b = (const float*)d_in[8];
    const float* att_fc_w = (const float*)d_in[9];
    const float* att_fc_b = (const float*)d_in[10];
    const float* w_i2h_zr = (const float*)d_in[11];
    const float* b_i2h_zr = (const float*)d_in[12];
    const float* w_h2h_zr = (const float*)d_in[13];
    const float* b_h2h_zr = (const float*)d_in[14];
    const float* w_i2h_t  = (const float*)d_in[15];
    const float* b_i2h_t  = (const float*)d_in[16];
    const float* w_h2h_t  = (const float*)d_in[17];
    const float* b_h2h_t  = (const float*)d_in[18];
    const float* fc0_w    = (const float*)d_in[19];
    const float* fc0_b    = (const float*)d_in[20];

    float* out     = (float*)d_out;
    float* out_att = out + Bv * Cv;

    cudaFuncSetAttribute(gru_mma,  cudaFuncAttributeMaxDynamicSharedMemorySize, 229376);
    cudaFuncSetAttribute(tagm_mma, cudaFuncAttributeMaxDynamicSharedMemorySize, 137216);

    float *p_xwf, *p_xwb, *p_xzr, *p_xt;
    cudaGetSymbolAddress((void**)&p_xwf, g_xw_f);
    cudaGetSymbolAddress((void**)&p_xwb, g_xw_b);
    cudaGetSymbolAddress((void**)&p_xzr, g_xzr);
    cudaGetSymbolAddress((void**)&p_xt,  g_xt);
    uint32_t *p_xh, *p_xl, *p_fh, *p_fl, *p_bh, *p_bl, *p_zh, *p_zl, *p_th, *p_tl;
    cudaGetSymbolAddress((void**)&p_xh, g_xh);     cudaGetSymbolAddress((void**)&p_xl, g_xl);
    cudaGetSymbolAddress((void**)&p_fh, g_wif_h);  cudaGetSymbolAddress((void**)&p_fl, g_wif_l);
    cudaGetSymbolAddress((void**)&p_bh, g_wib_h);  cudaGetSymbolAddress((void**)&p_bl, g_wib_l);
    cudaGetSymbolAddress((void**)&p_zh, g_wizr_h); cudaGetSymbolAddress((void**)&p_zl, g_wizr_l);
    cudaGetSymbolAddress((void**)&p_th, g_wit_h);  cudaGetSymbolAddress((void**)&p_tl, g_wit_l);

    // 0) conversions to split-bf16
    conv_x<<<32768, 256>>>(x);
    conv_w<<<3072, 256>>>(att_wi_f, p_fh, p_fl);
    conv_w<<<3072, 256>>>(att_wi_b, p_bh, p_bl);
    conv_w<<<2048, 256>>>(w_i2h_zr, p_zh, p_zl);
    conv_w<<<1024, 256>>>(w_i2h_t,  p_th, p_tl);

    // 1) input projections (tensor cores)
    proj_mma<<<dim3(48, 512), 128>>>(p_xh, p_xl, p_fh, p_fl, att_bi_f, p_xwf, G3);
    proj_mma<<<dim3(48, 512), 128>>>(p_xh, p_xl, p_bh, p_bl, att_bi_b, p_xwb, G3);
    proj_mma<<<dim3(32, 512), 128>>>(p_xh, p_xl, p_zh, p_zl, b_i2h_zr, p_xzr, G2);
    proj_mma<<<dim3(16, 512), 128>>>(p_xh, p_xl, p_th, p_tl, b_i2h_t,  p_xt,  Hv);

    // 2) bidirectional GRU — persistent, tensor cores, 256 thr
    gru_mma<<<128, 256, 229376>>>(att_wh_f, att_wh_b, att_bh_f, att_bh_b);

    // 3) attention gate
    att_kernel<<<Tv, 256>>>(att_fc_w, att_fc_b, out_att);

    // 4) TAGM — persistent, tensor cores, 256 thr
    tagm_mma<<<128, 256, 137216>>>(w_h2h_zr, b_h2h_zr, w_h2h_t, b_h2h_t);

    // 5) final projection
    fc0_kernel<<<Bv, 256>>>(fc0_w, fc0_b, out);
}

// round 8
// speedup vs baseline: 2.4942x; 1.5145x over previous
#include <cuda_runtime.h>
#include <cuda_bf16.h>
#include <math.h>
#include <stdint.h>

#define Bv 64
#define Tv 512
#define Iv 512
#define Hv 1024
#define Cv 128
#define G3 (3*Hv)
#define G2 (2*Hv)

// ---------------- static device scratch ----------------
__device__ float g_xw_f[(size_t)Tv*Bv*G3];
__device__ float g_xw_b[(size_t)Tv*Bv*G3];
__device__ float g_xzr [(size_t)Tv*Bv*G2];
__device__ float g_xt  [(size_t)Tv*Bv*Hv];
__device__ float g_att [Tv*Bv];

// packed bf16-pair words (word w = elems 2w (lo16), 2w+1 (hi16))
__device__ uint32_t g_xh[(size_t)32768*256], g_xl[(size_t)32768*256];
__device__ uint32_t g_wif_h[(size_t)3072*256],  g_wif_l[(size_t)3072*256];
__device__ uint32_t g_wib_h[(size_t)3072*256],  g_wib_l[(size_t)3072*256];
__device__ uint32_t g_wizr_h[(size_t)2048*256], g_wizr_l[(size_t)2048*256];
__device__ uint32_t g_wit_h[(size_t)1024*256],  g_wit_l[(size_t)1024*256];
// hidden-state histories, split-bf16 words [t][b][512]
__device__ uint32_t g_hf_h[(size_t)Tv*Bv*512], g_hf_l[(size_t)Tv*Bv*512];
__device__ uint32_t g_hb_h[(size_t)Tv*Bv*512], g_hb_l[(size_t)Tv*Bv*512];
__device__ uint32_t g_ht_h[(size_t)Tv*Bv*512], g_ht_l[(size_t)Tv*Bv*512];

__device__ unsigned g_bar_cnt[3*32];
__device__ unsigned g_bar_gen[3*32];

__device__ __forceinline__ float sigmoidf_(float x) { return 1.0f / (1.0f + expf(-x)); }
__device__ __forceinline__ float lo16f(uint32_t w) { return __uint_as_float(w << 16); }
__device__ __forceinline__ float hi16f(uint32_t w) { return __uint_as_float(w & 0xffff0000u); }
__device__ __forceinline__ uint32_t bfbits(float x) {
    __nv_bfloat16 h = __float2bfloat16(x);
    return (uint32_t)*reinterpret_cast<unsigned short*>(&h);
}
__device__ __forceinline__ void split2(float x0, float x1, uint32_t& wh, uint32_t& wl) {
    uint32_t h0 = bfbits(x0), h1 = bfbits(x1);
    float r0 = x0 - __uint_as_float(h0 << 16);
    float r1 = x1 - __uint_as_float(h1 << 16);
    wh = h0 | (h1 << 16);
    wl = bfbits(r0) | (bfbits(r1) << 16);
}

__device__ __forceinline__ void mma16816(float* d,
    uint32_t a0, uint32_t a1, uint32_t a2, uint32_t a3, uint32_t b0, uint32_t b1) {
    asm volatile(
        "mma.sync.aligned.m16n8k16.row.col.f32.bf16.bf16.f32 "
        "{%0,%1,%2,%3},{%4,%5,%6,%7},{%8,%9},{%0,%1,%2,%3};"
        : "+f"(d[0]), "+f"(d[1]), "+f"(d[2]), "+f"(d[3])
        : "r"(a0), "r"(a1), "r"(a2), "r"(a3), "r"(b0), "r"(b1));
}

// lightweight grid barrier: CG-style release/acquire, no per-thread fence,
// no nanosleep. Sense-relative (works across graph replays).
__device__ __forceinline__ void grid_bar(int grp, unsigned nb) {
    __syncthreads();
    if (threadIdx.x == 0) {
        unsigned* cnt = &g_bar_cnt[grp*32];
        unsigned* gen = &g_bar_gen[grp*32];
        unsigned g, old;
        asm volatile("ld.relaxed.gpu.u32 %0, [%1];" : "=r"(g) : "l"(gen) : "memory");
        asm volatile("atom.acq_rel.gpu.add.u32 %0, [%1], %2;"
                     : "=r"(old) : "l"(cnt), "r"(1u) : "memory");
        if (old == nb - 1) {
            asm volatile("st.relaxed.gpu.u32 [%0], %1;" :: "l"(cnt), "r"(0u) : "memory");
            asm volatile("st.release.gpu.u32 [%0], %1;" :: "l"(gen), "r"(g + 1u) : "memory");
        } else {
            unsigned cur;
            do {
                asm volatile("ld.acquire.gpu.u32 %0, [%1];" : "=r"(cur) : "l"(gen) : "memory");
            } while (cur == g);
        }
    }
    __syncthreads();
}

// ============================================================================
// converters
// ============================================================================
__global__ void conv_x(const float* __restrict__ x) {
    int r = blockIdx.x, wi = threadIdx.x;          // r = t*64+b
    int b = r & 63, t = r >> 6;
    float2 v = ((const float2*)x)[((size_t)b * Tv + t) * 256 + wi];
    uint32_t wh, wl; split2(v.x, v.y, wh, wl);
    g_xh[(size_t)r * 256 + wi] = wh;
    g_xl[(size_t)r * 256 + wi] = wl;
}
__global__ void conv_w(const float* __restrict__ src,
                       uint32_t* __restrict__ hi, uint32_t* __restrict__ lo) {
    size_t i = (size_t)blockIdx.x * 256 + threadIdx.x;
    float2 v = ((const float2*)src)[i];
    uint32_t wh, wl; split2(v.x, v.y, wh, wl);
    hi[i] = wh; lo[i] = wl;
}

// ============================================================================
// proj via bf16-split mma: out[r,n] = x[r,:].W[n,:] + bias[n]; tile 64x64xK512
// ============================================================================
__global__ void __launch_bounds__(128) proj_mma(
    const uint32_t* __restrict__ Ah, const uint32_t* __restrict__ Al,
    const uint32_t* __restrict__ Wh, const uint32_t* __restrict__ Wl,
    const float* __restrict__ bias, float* __restrict__ out, int N)
{
    __shared__ uint32_t sA[2*64*36], sB[2*64*36];   // hi at 0, lo at +2304
    const int tid = threadIdx.x, w = tid >> 5, lane = tid & 31;
    const int g = lane >> 2, tg = lane & 3;
    const int m0 = blockIdx.y * 64, n0 = blockIdx.x * 64;

    float D[8][4] = {};

    #pragma unroll 1
    for (int st = 0; st < 8; st++) {
        const int kw0 = st * 32;
        __syncthreads();
        #pragma unroll
        for (int q = 0; q < 4; q++) {
            int idx = tid + 128 * q;
            int row = idx >> 3, seg = idx & 7;
            *(uint4*)&sA[row*36 + seg*4]        = *(const uint4*)(Ah + (size_t)(m0+row)*256 + kw0 + seg*4);
            *(uint4*)&sA[2304 + row*36 + seg*4] = *(const uint4*)(Al + (size_t)(m0+row)*256 + kw0 + seg*4);
            *(uint4*)&sB[row*36 + seg*4]        = *(const uint4*)(Wh + (size_t)(n0+row)*256 + kw0 + seg*4);
            *(uint4*)&sB[2304 + row*36 + seg*4] = *(const uint4*)(Wl + (size_t)(n0+row)*256 + kw0 + seg*4);
        }
        __syncthreads();
        #pragma unroll
        for (int ks = 0; ks < 4; ks++) {
            int ra = (16*w + g) * 36 + ks * 8, rb = ra + 8*36;
            uint32_t a0h = sA[ra+tg],      a2h = sA[ra+4+tg];
            uint32_t a1h = sA[rb+tg],      a3h = sA[rb+4+tg];
            uint32_t a0l = sA[2304+ra+tg], a2l = sA[2304+ra+4+tg];
            uint32_t a1l = sA[2304+rb+tg], a3l = sA[2304+rb+4+tg];
            #pragma unroll
            for (int nt = 0; nt < 8; nt++) {
                int rn = (nt*8 + g) * 36 + ks * 8;
                uint32_t b0h = sB[rn+tg],      b1h = sB[rn+4+tg];
                uint32_t b0l = sB[2304+rn+tg], b1l = sB[2304+rn+4+tg];
                mma16816(D[nt], a0h,a1h,a2h,a3h, b0h,b1h);
                mma16816(D[nt], a0h,a1h,a2h,a3h, b0l,b1l);
                mma16816(D[nt], a0l,a1l,a2l,a3l, b0h,b1h);
            }
        }
    }

    const int r0 = m0 + 16*w + g, r1 = r0 + 8;
    #pragma unroll
    for (int nt = 0; nt < 8; nt++) {
        int c = n0 + nt*8 + tg*2;
        float2 bi = *(const float2*)(bias + c);
        *(float2*)(out + (size_t)r0 * N + c) = make_float2(D[nt][0]+bi.x, D[nt][1]+bi.y);
        *(float2*)(out + (size_t)r1 * N + c) = make_float2(D[nt][2]+bi.x, D[nt][3]+bi.y);
    }
}

// ============================================================================
// Persistent bidirectional GRU, tensor cores, 256 threads.
//   128 blocks. dir = bid>>6, 16 hidden cols per block.
//   warp: mt = w&3 (16 batch rows), ch = w>>2 (8 of the 16 cols).
//   Register-staged h pipeline (LDG 2 stages ahead; STS right before bar).
// ============================================================================
__global__ void __launch_bounds__(256) gru_mma(
    const float* __restrict__ wh_f, const float* __restrict__ wh_b,
    const float* __restrict__ bh_f, const float* __restrict__ bh_b)
{
    extern __shared__ uint32_t smem[];
    uint32_t* sWh = smem;            // 24576 words
    uint32_t* sWl = smem + 24576;    // 24576
    uint32_t* sH  = smem + 49152;    // 8192

    const int tid = threadIdx.x, w = tid >> 5, lane = tid & 31;
    const int g = lane >> 2, tg = lane & 3;
    const int mt = w & 3, ch = w >> 2;
    const int dir = blockIdx.x >> 6;
    const int j0 = (blockIdx.x & 63) * 16;

    const float* wh = dir ? wh_b : wh_f;
    const float* bh = dir ? bh_b : bh_f;
    const float* xw = dir ? g_xw_b : g_xw_f;
    uint32_t* Hh = dir ? g_hb_h : g_hf_h;
    uint32_t* Hl = dir ? g_hb_l : g_hf_l;

    // preload + split weights: virtual rows 0..47 (16 r, 16 z, 16 n)
    for (int i = tid; i < 48 * 512; i += 256) {
        int vr = i >> 9, wd = i & 511;
        int grow = (vr >> 4) * Hv + j0 + (vr & 15);
        float2 v = *(const float2*)(wh + (size_t)grow * Hv + wd * 2);
        uint32_t wh_, wl_; split2(v.x, v.y, wh_, wl_);
        int ad = vr * 512 + (wd ^ ((vr & 7) << 2));
        sWh[ad] = wh_; sWl[ad] = wl_;
    }
    __syncthreads();

    // fixed per-thread geometry
    const int j = j0 + ch * 8 + tg * 2;
    const float2 br_ = *(const float2*)(bh + j);
    const float2 bz_ = *(const float2*)(bh + Hv + j);
    const float2 bn_ = *(const float2*)(bh + 2*Hv + j);
    const int r0 = (16*mt + g) * 32, r1 = (16*mt + 8 + g) * 32;
    const int sza = g << 2;
    const int lrow = tid >> 3, lseg = tid & 7;
    const int lgo  = lrow * 512 + lseg * 4;              // global word offset within slab
    const int sad0 = lrow * 32 + ((lseg * 4) ^ ((lrow & 7) << 2));
    const int sad1 = sad0 + 1024;                        // row+32 has same low bits

    for (int s = 0; s < Tv; s++) {
        const int t = dir ? (Tv - 1 - s) : s;
        const int tp = dir ? t + 1 : t - 1;
        const float* xwt = xw + (size_t)t * 64 * G3;

        // x-gate prefetch (independent of h -> overlaps the barrier spin)
        float2 xrv[2], xzv[2], xnv[2];
        #pragma unroll
        for (int rw = 0; rw < 2; rw++) {
            int b = 16*mt + g + 8*rw;
            const float* xr = xwt + (size_t)b * G3;
            xrv[rw] = *(const float2*)(xr + j);
            xzv[rw] = *(const float2*)(xr + Hv + j);
            xnv[rw] = *(const float2*)(xr + 2*Hv + j);
        }

        float D[3][4] = {};
        uint32_t hpw[2] = {0,0}, plw[2] = {0,0};

        if (s) {
            grid_bar(dir, 64);
            const uint32_t* ph = Hh + (size_t)tp * (64*512);
            const uint32_t* pl = Hl + (size_t)tp * (64*512);
            // epilogue h_prev prefetch
            #pragma unroll
            for (int rw = 0; rw < 2; rw++) {
                int b = 16*mt + g + 8*rw;
                hpw[rw] = ph[(size_t)b*512 + (j>>1)];
                plw[rw] = pl[(size_t)b*512 + (j>>1)];
            }

            // register-staged mainloop
            uint4 ah0, al0, ah1, al1, bh0, bl0, bh1, bl1;
            #define LDGST(st, H0, L0, H1, L1) do { \
                const uint32_t* ph_ = ph + (st)*32 + lgo; \
                const uint32_t* pl_ = pl + (st)*32 + lgo; \
                H0 = *(const uint4*)ph_;          L0 = *(const uint4*)pl_; \
                H1 = *(const uint4*)(ph_+16384);  L1 = *(const uint4*)(pl_+16384); \
            } while(0)
            #define STSH(BB, H0, L0, H1, L1) do { \
                uint32_t* bp = sH + (BB)*4096; \
                *(uint4*)(bp + sad0) = H0;        *(uint4*)(bp + sad0 + 2048) = L0; \
                *(uint4*)(bp + sad1) = H1;        *(uint4*)(bp + sad1 + 2048) = L1; \
            } while(0)
            #define COMPUTE(ST, BB) do { \
                const uint32_t* hb_ = sH + (BB)*4096; \
                _Pragma("unroll") \
                for (int ks = 0; ks < 4; ks++) { \
                    int w0 = (ks*8+tg)^sza, w1 = (ks*8+4+tg)^sza; \
                    uint32_t a0h=hb_[r0+w0], a1h=hb_[r1+w0], a2h=hb_[r0+w1], a3h=hb_[r1+w1]; \
                    uint32_t a0l=hb_[2048+r0+w0], a1l=hb_[2048+r1+w0]; \
                    uint32_t a2l=hb_[2048+r0+w1], a3l=hb_[2048+r1+w1]; \
                    _Pragma("unroll") \
                    for (int gate = 0; gate < 3; gate++) { \
                        int vr = gate*16 + ch*8 + g; \
                        int wb0 = vr*512 + (((ST)*32+ks*8+tg) ^ ((vr&7)<<2)); \
                        int wb1 = vr*512 + (((ST)*32+ks*8+4+tg) ^ ((vr&7)<<2)); \
                        uint32_t b0h = sWh[wb0], b1h = sWh[wb1]; \
                        uint32_t b0l = sWl[wb0], b1l = sWl[wb1]; \
                        mma16816(D[gate], a0h,a1h,a2h,a3h, b0h,b1h); \
                        mma16816(D[gate], a0h,a1h,a2h,a3h, b0l,b1l); \
                        mma16816(D[gate], a0l,a1l,a2l,a3l, b0h,b1h); \
                    } \
                } \
            } while(0)

            LDGST(0, ah0, al0, ah1, al1);
            LDGST(1, bh0, bl0, bh1, bl1);
            #pragma unroll 1
            for (int st2 = 0; st2 < 16; st2 += 2) {
                STSH(0, ah0, al0, ah1, al1);
                if (st2 < 14) LDGST(st2+2, ah0, al0, ah1, al1);
                __syncthreads();
                COMPUTE(st2, 0);
                STSH(1, bh0, bl0, bh1, bl1);
                if (st2 < 14) LDGST(st2+3, bh0, bl0, bh1, bl1);
                __syncthreads();
                COMPUTE(st2+1, 1);
            }
            #undef LDGST
            #undef STSH
            #undef COMPUTE
        }

        // epilogue: gates + h update + split store
        uint32_t* oh = Hh + (size_t)t * (64*512);
        uint32_t* ol = Hl + (size_t)t * (64*512);
        #pragma unroll
        for (int rw = 0; rw < 2; rw++) {
            int b = 16*mt + g + 8*rw;
            float hp0 = 0.f, hp1 = 0.f;
            if (s) {
                hp0 = lo16f(hpw[rw]) + lo16f(plw[rw]);
                hp1 = hi16f(hpw[rw]) + hi16f(plw[rw]);
            }
            float r0v = sigmoidf_(xrv[rw].x + D[0][rw*2+0] + br_.x);
            float r1v = sigmoidf_(xrv[rw].y + D[0][rw*2+1] + br_.y);
            float z0 = sigmoidf_(xzv[rw].x + D[1][rw*2+0] + bz_.x);
            float z1 = sigmoidf_(xzv[rw].y + D[1][rw*2+1] + bz_.y);
            float n0 = tanhf(xnv[rw].x + r0v * (D[2][rw*2+0] + bn_.x));
            float n1 = tanhf(xnv[rw].y + r1v * (D[2][rw*2+1] + bn_.y));
            float h0 = (1.f - z0) * n0 + z0 * hp0;
            float h1 = (1.f - z1) * n1 + z1 * hp1;
            uint32_t sh_, sl_; split2(h0, h1, sh_, sl_);
            oh[(size_t)b*512 + (j>>1)] = sh_;
            ol[(size_t)b*512 + (j>>1)] = sl_;
        }
    }
}

// ============================================================================
// attention: att[t,b] = sigmoid(3*(hf.w[0:H] + hb.w[H:2H] + b))
// ============================================================================
__global__ void att_kernel(const float* __restrict__ fcw, const float* __restrict__ fcb,
                           float* __restrict__ out_att)
{
    const int t = blockIdx.x;
    const int w = threadIdx.x >> 5, lane = threadIdx.x & 31;
    for (int rep = 0; rep < 8; rep++) {
        int b = w + rep * 8;
        size_t o = (size_t)(t * 64 + b) * 512;
        float acc = 0.0f;
        for (int k = lane; k < 512; k += 32) {
            uint32_t hw = g_hf_h[o + k], lw = g_hf_l[o + k];
            float2 wv = *(const float2*)(fcw + 2 * k);
            acc += (lo16f(hw) + lo16f(lw)) * wv.x + (hi16f(hw) + hi16f(lw)) * wv.y;
            hw = g_hb_h[o + k]; lw = g_hb_l[o + k];
            wv = *(const float2*)(fcw + Hv + 2 * k);
            acc += (lo16f(hw) + lo16f(lw)) * wv.x + (hi16f(hw) + hi16f(lw)) * wv.y;
        }
        #pragma unroll
        for (int of = 16; of; of >>= 1) acc += __shfl_xor_sync(0xffffffffu, acc, of);
        if (lane == 0) {
            float a = sigmoidf_(3.0f * (acc + fcb[0]));
            g_att[t * 64 + b] = a;
            out_att[(size_t)b * Tv + t] = a;
        }
    }
}

// ============================================================================
// Persistent TAGM, tensor cores, 256 threads: 128 blocks, 8 cols/block.
//   warp: mt = w&3 (16 batch rows), kh = w>>2 (2 of the 4 ks per stage).
//   Register-staged h pipeline; k-half combine via smem.
// ============================================================================
__global__ void __launch_bounds__(256) tagm_mma(
    const float* __restrict__ wzr, const float* __restrict__ bzr,
    const float* __restrict__ wt,  const float* __restrict__ bt)
{
    extern __shared__ uint32_t smem[];
    uint32_t* sWh = smem;            // 12288 words
    uint32_t* sWl = smem + 12288;    // 12288
    uint32_t* sH  = smem + 24576;    // 8192
    float*    red = (float*)(smem + 32768);  // 1536 floats

    const int tid = threadIdx.x, w = tid >> 5, lane = tid & 31;
    const int g = lane >> 2, tg = lane & 3;
    const int mt = w & 3, kh = w >> 2;
    const int j0 = blockIdx.x * 8;

    // preload weights: rows 0..7 r, 8..15 z, 16..23 t-hat
    for (int i = tid; i < 24 * 512; i += 256) {
        int vr = i >> 9, wd = i & 511;
        int gate = vr >> 3, jj = vr & 7;
        const float* src = (gate < 2) ? (wzr + (size_t)(gate * Hv + j0 + jj) * Hv)
                                      : (wt + (size_t)(j0 + jj) * Hv);
        float2 v = *(const float2*)(src + wd * 2);
        uint32_t wh_, wl_; split2(v.x, v.y, wh_, wl_);
        int ad = vr * 512 + (wd ^ ((vr & 7) << 2));
        sWh[ad] = wh_; sWl[ad] = wl_;
    }
    __syncthreads();

    const int j = j0 + tg * 2;
    const float2 br_ = *(const float2*)(bzr + j);
    const float2 bz_ = *(const float2*)(bzr + Hv + j);
    const float2 bt_ = *(const float2*)(bt + j);
    const int r0 = (16*mt + g) * 32, r1 = (16*mt + 8 + g) * 32;
    const int sza = g << 2;
    const int lrow = tid >> 3, lseg = tid & 7;
    const int lgo  = lrow * 512 + lseg * 4;
    const int sad0 = lrow * 32 + ((lseg * 4) ^ ((lrow & 7) << 2));
    const int sad1 = sad0 + 1024;

    for (int s = 0; s < Tv; s++) {
        // epilogue input prefetch (kh==0 warps only use it)
        float2 xrv[1], xzv[1], xtv[1], xrv1[1], xzv1[1], xtv1[1];
        float av[2] = {0,0};
        float2 exr[2], exz[2], ext[2];
        if (kh == 0) {
            #pragma unroll
            for (int rw = 0; rw < 2; rw++) {
                int b = 16*mt + g + 8*rw;
                av[rw] = g_att[s * 64 + b];
                exr[rw] = *(const float2*)(g_xzr + (size_t)(s*64 + b) * G2 + j);
                exz[rw] = *(const float2*)(g_xzr + (size_t)(s*64 + b) * G2 + Hv + j);
                ext[rw] = *(const float2*)(g_xt  + (size_t)(s*64 + b) * Hv + j);
            }
        }
        (void)xrv; (void)xzv; (void)xtv; (void)xrv1; (void)xzv1; (void)xtv1;

        float D[3][4] = {};
        uint32_t hpw[2] = {0,0}, plw[2] = {0,0};

        if (s) {
            grid_bar(2, 128);
            const uint32_t* ph = g_ht_h + (size_t)(s - 1) * (64*512);
            const uint32_t* pl = g_ht_l + (size_t)(s - 1) * (64*512);
            if (kh == 0) {
                #pragma unroll
                for (int rw = 0; rw < 2; rw++) {
                    int b = 16*mt + g + 8*rw;
                    hpw[rw] = ph[(size_t)b*512 + (j>>1)];
                    plw[rw] = pl[(size_t)b*512 + (j>>1)];
                }
            }

            uint4 ah0, al0, ah1, al1, bh0, bl0, bh1, bl1;
            #define LDGST(st, H0, L0, H1, L1) do { \
                const uint32_t* ph_ = ph + (st)*32 + lgo; \
                const uint32_t* pl_ = pl + (st)*32 + lgo; \
                H0 = *(const uint4*)ph_;          L0 = *(const uint4*)pl_; \
                H1 = *(const uint4*)(ph_+16384);  L1 = *(const uint4*)(pl_+16384); \
            } while(0)
            #define STSH(BB, H0, L0, H1, L1) do { \
                uint32_t* bp = sH + (BB)*4096; \
                *(uint4*)(bp + sad0) = H0;        *(uint4*)(bp + sad0 + 2048) = L0; \
                *(uint4*)(bp + sad1) = H1;        *(uint4*)(bp + sad1 + 2048) = L1; \
            } while(0)
            #define COMPUTE(ST, BB) do { \
                const uint32_t* hb_ = sH + (BB)*4096; \
                _Pragma("unroll") \
                for (int ki = 0; ki < 2; ki++) { \
                    int ks = 2*kh + ki; \
                    int w0 = (ks*8+tg)^sza, w1 = (ks*8+4+tg)^sza; \
                    uint32_t a0h=hb_[r0+w0], a1h=hb_[r1+w0], a2h=hb_[r0+w1], a3h=hb_[r1+w1]; \
                    uint32_t a0l=hb_[2048+r0+w0], a1l=hb_[2048+r1+w0]; \
                    uint32_t a2l=hb_[2048+r0+w1], a3l=hb_[2048+r1+w1]; \
                    _Pragma("unroll") \
                    for (int gate = 0; gate < 3; gate++) { \
                        int vr = gate*8 + g; \
                        int wb0 = vr*512 + (((ST)*32+ks*8+tg) ^ (g << 2)); \
                        int wb1 = vr*512 + (((ST)*32+ks*8+4+tg) ^ (g << 2)); \
                        uint32_t b0h = sWh[wb0], b1h = sWh[wb1]; \
                        uint32_t b0l = sWl[wb0], b1l = sWl[wb1]; \
                        mma16816(D[gate], a0h,a1h,a2h,a3h, b0h,b1h); \
                        mma16816(D[gate], a0h,a1h,a2h,a3h, b0l,b1l); \
                        mma16816(D[gate], a0l,a1l,a2l,a3l, b0h,b1h); \
                    } \
                } \
            } while(0)

            LDGST(0, ah0, al0, ah1, al1);
            LDGST(1, bh0, bl0, bh1, bl1);
            #pragma unroll 1
            for (int st2 = 0; st2 < 16; st2 += 2) {
                STSH(0, ah0, al0, ah1, al1);
                if (st2 < 14) LDGST(st2+2, ah0, al0, ah1, al1);
                __syncthreads();
                COMPUTE(st2, 0);
                STSH(1, bh0, bl0, bh1, bl1);
                if (st2 < 14) LDGST(st2+3, bh0, bl0, bh1, bl1);
                __syncthreads();
                COMPUTE(st2+1, 1);
            }
            #undef LDGST
            #undef STSH
            #undef COMPUTE

            // combine k-halves: warps 4..7 publish, warps 0..3 accumulate
            __syncthreads();
            if (kh == 1) {
                float* rp = red + ((w - 4) * 32 + lane) * 12;
                #pragma unroll
                for (int gate = 0; gate < 3; gate++)
                    #pragma unroll
                    for (int e = 0; e < 4; e++) rp[gate*4 + e] = D[gate][e];
            }
            __syncthreads();
            if (kh == 0) {
                const float* rp = red + (w * 32 + lane) * 12;
                #pragma unroll
                for (int gate = 0; gate < 3; gate++)
                    #pragma unroll
                    for (int e = 0; e < 4; e++) D[gate][e] += rp[gate*4 + e];
            }
        }

        // epilogue (warps 0..3 only)
        if (kh == 0) {
            uint32_t* oh = g_ht_h + (size_t)s * (64*512);
            uint32_t* ol = g_ht_l + (size_t)s * (64*512);
            #pragma unroll
            for (int rw = 0; rw < 2; rw++) {
                int b = 16*mt + g + 8*rw;
                float hp0 = 0.f, hp1 = 0.f;
                if (s) {
                    hp0 = lo16f(hpw[rw]) + lo16f(plw[rw]);
                    hp1 = hi16f(hpw[rw]) + hi16f(plw[rw]);
                }
                float r0v = sigmoidf_(exr[rw].x + D[0][rw*2+0] + br_.x);
                float r1v = sigmoidf_(exr[rw].y + D[0][rw*2+1] + br_.y);
                float z0 = sigmoidf_(exz[rw].x + D[1][rw*2+0] + bz_.x);
                float z1 = sigmoidf_(exz[rw].y + D[1][rw*2+1] + bz_.y);
                float t0 = tanhf(ext[rw].x + r0v * (D[2][rw*2+0] + bt_.x));
                float t1 = tanhf(ext[rw].y + r1v * (D[2][rw*2+1] + bt_.y));
                float h0 = av[rw] * (z0 * t0 + (1.f - z0) * hp0);
                float h1 = av[rw] * (z1 * t1 + (1.f - z1) * hp1);
                uint32_t sh_, sl_; split2(h0, h1, sh_, sl_);
                oh[(size_t)b*512 + (j>>1)] = sh_;
                ol[(size_t)b*512 + (j>>1)] = sl_;
            }
        }
    }
}

// ============================================================================
// fc0
// ============================================================================
__global__ void fc0_kernel(const float* __restrict__ w, const float* __restrict__ bias,
                           float* __restrict__ out)
{
    const int b = blockIdx.x;
    const int wp = threadIdx.x >> 5, lane = threadIdx.x & 31;
    size_t o = (size_t)((Tv - 1) * 64 + b) * 512;
    for (int c = wp; c < Cv; c += 8) {
        float acc = 0.0f;
        for (int k = lane; k < 512; k += 32) {
            uint32_t hw = g_ht_h[o + k], lw = g_ht_l[o + k];
            float2 wv = *(const float2*)(w + (size_t)c * Hv + 2 * k);
            acc += (lo16f(hw) + lo16f(lw)) * wv.x + (hi16f(hw) + hi16f(lw)) * wv.y;
        }
        #pragma unroll
        for (int of = 16; of; of >>= 1) acc += __shfl_xor_sync(0xffffffffu, acc, of);
        if (lane == 0) out[(size_t)b * Cv + c] = acc + bias[c];
    }
}

// ============================================================================
extern "C" void kernel_launch(void* const* d_in, const int* in_sizes, int n_in,
                              void* d_out, int out_size)
{
    const float* x        = (const float*)d_in[0];
    const float* att_wi_f = (const float*)d_in[1];
    const float* att_wh_f = (const float*)d_in[2];
    const float* att_bi_f = (const float*)d_in[3];
    const float* att_bh_f = (const float*)d_in[4];
    const float* att_wi_b = (const float*)d_in[5];
    const float* att_wh_b = (const float*)d_in[6];
    const float* att_bi_b = (const float*)d_in[7];
    const float* att_bh_b = (const float*)d_in[8];
    const float* att_fc_w = (const float*)d_in[9];
    const float* att_fc_b = (const float*)d_in[10];
    const float* w_i2h_zr = (const float*)d_in[11];
    const float* b_i2h_zr = (const float*)d_in[12];
    const float* w_h2h_zr = (const float*)d_in[13];
    const float* b_h2h_zr = (const float*)d_in[14];
    const float* w_i2h_t  = (const float*)d_in[15];
    const float* b_i2h_t  = (const float*)d_in[16];
    const float* w_h2h_t  = (const float*)d_in[17];
    const float* b_h2h_t  = (const float*)d_in[18];
    const float* fc0_w    = (const float*)d_in[19];
    const float* fc0_b    = (const float*)d_in[20];

    float* out     = (float*)d_out;
    float* out_att = out + Bv * Cv;

    cudaFuncSetAttribute(gru_mma,  cudaFuncAttributeMaxDynamicSharedMemorySize, 229376);
    cudaFuncSetAttribute(tagm_mma, cudaFuncAttributeMaxDynamicSharedMemorySize, 137216);

    float *p_xwf, *p_xwb, *p_xzr, *p_xt;
    cudaGetSymbolAddress((void**)&p_xwf, g_xw_f);
    cudaGetSymbolAddress((void**)&p_xwb, g_xw_b);
    cudaGetSymbolAddress((void**)&p_xzr, g_xzr);
    cudaGetSymbolAddress((void**)&p_xt,  g_xt);
    uint32_t *p_xh, *p_xl, *p_fh, *p_fl, *p_bh, *p_bl, *p_zh, *p_zl, *p_th, *p_tl;
    cudaGetSymbolAddress((void**)&p_xh, g_xh);     cudaGetSymbolAddress((void**)&p_xl, g_xl);
    cudaGetSymbolAddress((void**)&p_fh, g_wif_h);  cudaGetSymbolAddress((void**)&p_fl, g_wif_l);
    cudaGetSymbolAddress((void**)&p_bh, g_wib_h);  cudaGetSymbolAddress((void**)&p_bl, g_wib_l);
    cudaGetSymbolAddress((void**)&p_zh, g_wizr_h); cudaGetSymbolAddress((void**)&p_zl, g_wizr_l);
    cudaGetSymbolAddress((void**)&p_th, g_wit_h);  cudaGetSymbolAddress((void**)&p_tl, g_wit_l);

    // 0) conversions to split-bf16
    conv_x<<<32768, 256>>>(x);
    conv_w<<<3072, 256>>>(att_wi_f, p_fh, p_fl);
    conv_w<<<3072, 256>>>(att_wi_b, p_bh, p_bl);
    conv_w<<<2048, 256>>>(w_i2h_zr, p_zh, p_zl);
    conv_w<<<1024, 256>>>(w_i2h_t,  p_th, p_tl);

    // 1) input projections (tensor cores)
    proj_mma<<<dim3(48, 512), 128>>>(p_xh, p_xl, p_fh, p_fl, att_bi_f, p_xwf, G3);
    proj_mma<<<dim3(48, 512), 128>>>(p_xh, p_xl, p_bh, p_bl, att_bi_b, p_xwb, G3);
    proj_mma<<<dim3(32, 512), 128>>>(p_xh, p_xl, p_zh, p_zl, b_i2h_zr, p_xzr, G2);
    proj_mma<<<dim3(16, 512), 128>>>(p_xh, p_xl, p_th, p_tl, b_i2h_t,  p_xt,  Hv);

    // 2) bidirectional GRU — persistent, tensor cores
    gru_mma<<<128, 256, 229376>>>(att_wh_f, att_wh_b, att_bh_f, att_bh_b);

    // 3) attention gate
    att_kernel<<<Tv, 256>>>(att_fc_w, att_fc_b, out_att);

    // 4) TAGM — persistent, tensor cores
    tagm_mma<<<128, 256, 137216>>>(w_h2h_zr, b_h2h_zr, w_h2h_t, b_h2h_t);

    // 5) final projection
    fc0_kernel<<<Bv, 256>>>(fc0_w, fc0_b, out);
}